// round 5
// baseline (speedup 1.0000x reference)
#include <cuda_runtime.h>

#define BB    64
#define WW    64
#define FNSEQ 8192
#define NTR   8201
#define NTP   8320
#define NMD   16
#define NSPL  10
#define TRG   832
#define TCA   32

typedef unsigned long long u64;

__device__ float g_v0[BB * WW * NTP];
__device__ float g_v1[BB * WW * NTP];
__device__ u64   g_basis2[NTP * 32];        // [t][kk] dup'd (c,c)/(s,s)
__device__ float g_basisT[32 * NTP];        // [kk][t]
__device__ u64   g_cw2[5 * WW * WW];        // [l][i][o] dup'd
__device__ float g_fpart[NSPL * BB * WW * 32];
__device__ u64   g_ab2[BB * 32 * WW];       // [b][kk][o] dup'd

__device__ __forceinline__ float gelu_f(float x) {
    return 0.5f * x * (1.0f + erff(x * 0.70710678118654752f));
}
__device__ __forceinline__ u64 pk2(float v) {
    u64 r; asm("mov.b64 %0, {%1, %1};" : "=l"(r) : "f"(v)); return r;
}
__device__ __forceinline__ void fma2(u64& d, u64 a, u64 b) {
    asm("fma.rn.f32x2 %0, %1, %2, %0;" : "+l"(d) : "l"(a), "l"(b));
}
__device__ __forceinline__ float2 up2(u64 v) {
    float2 f; asm("mov.b64 {%0, %1}, %2;" : "=f"(f.x), "=f"(f.y) : "l"(v)); return f;
}

// acc[4][4]: A01/A23 dup'd broadcast axis, B01/B23 packed pairs
#define FMA2_4x4(A01, A23, B01, B23)            \
    fma2(acc[0][0], (A01).x, (B01).x);          \
    fma2(acc[0][1], (A01).x, (B01).y);          \
    fma2(acc[0][2], (A01).x, (B23).x);          \
    fma2(acc[0][3], (A01).x, (B23).y);          \
    fma2(acc[1][0], (A01).y, (B01).x);          \
    fma2(acc[1][1], (A01).y, (B01).y);          \
    fma2(acc[1][2], (A01).y, (B23).x);          \
    fma2(acc[1][3], (A01).y, (B23).y);          \
    fma2(acc[2][0], (A23).x, (B01).x);          \
    fma2(acc[2][1], (A23).x, (B01).y);          \
    fma2(acc[2][2], (A23).x, (B23).x);          \
    fma2(acc[2][3], (A23).x, (B23).y);          \
    fma2(acc[3][0], (A23).y, (B01).x);          \
    fma2(acc[3][1], (A23).y, (B01).y);          \
    fma2(acc[3][2], (A23).y, (B23).x);          \
    fma2(acc[3][3], (A23).y, (B23).y);

__global__ void k_basis() {
    int t = blockIdx.x * 128 + threadIdx.x;
    if (t >= NTP) return;
#pragma unroll
    for (int k = 0; k < NMD; k++) {
        int r = (k * t) % NTR;
        float ang = (float)((double)r * (6.283185307179586 / (double)NTR));
        float s, c;
        sincosf(ang, &s, &c);
        g_basis2[t * 32 + k]       = pk2(c);
        g_basis2[t * 32 + NMD + k] = pk2(s);
        g_basisT[k * NTP + t]         = c;
        g_basisT[(NMD + k) * NTP + t] = s;
    }
}

__global__ void k_prep(const float* __restrict__ cw) {
    int idx = blockIdx.x * 128 + threadIdx.x;   // over 5*64*64
    if (idx >= 5 * WW * WW) return;
    int l = idx >> 12, r = idx & 4095, i = r >> 6, o = r & 63;
    g_cw2[idx] = pk2(cw[l * WW * WW + o * WW + i]);
}

__global__ void k_lift(const float* __restrict__ x,
                       const float* __restrict__ lw,
                       const float* __restrict__ lb) {
    int b = blockIdx.x;
    int t = blockIdx.y * 128 + threadIdx.x;
    if (t >= NTP) return;
    if (t >= NTR) {
#pragma unroll 4
        for (int i = 0; i < WW; i++) g_v1[(b * WW + i) * NTP + t] = 0.0f;
    }
    if (t >= FNSEQ) {
#pragma unroll 4
        for (int i = 0; i < WW; i++) g_v0[(b * WW + i) * NTP + t] = 0.0f;
        return;
    }
    float x0 = x[(b * FNSEQ + t) * 2 + 0];
    float x1 = x[(b * FNSEQ + t) * 2 + 1];
#pragma unroll 4
    for (int i = 0; i < WW; i++) {
        g_v0[(b * WW + i) * NTP + t] =
            fmaf(x0, __ldg(&lw[i]), fmaf(x1, __ldg(&lw[WW + i]), __ldg(&lb[i])));
    }
}

// forward restricted DFT partials: F[b,i,k] over t-split s (f32x2)
__global__ void __launch_bounds__(128) k_fwd(int src) {
    const float* __restrict__ vin = src ? g_v1 : g_v0;
    __shared__ __align__(16) float vsT[TCA][WW + 4];   // stride 68 f32 (272B, 16B-mult)
    __shared__ __align__(16) u64 bsS2[TCA][32];        // [tt][kk] dup'd
    int b = blockIdx.x, s = blockIdx.y, tid = threadIdx.x;
    int ti = tid & 15, tk = tid >> 4;
    int i0 = ti * 4, k0 = tk * 4;
    u64 acc[4][2] = {};    // [k][i-pair]
    const int tbeg = s * TRG;
    for (int tc = 0; tc < TRG; tc += TCA) {
        int tbase = tbeg + tc;
#pragma unroll
        for (int r = 0; r < 16; r++) {
            int idx = tid + 128 * r;
            int i = idx >> 5, tt = idx & 31;
            vsT[tt][i] = vin[(b * WW + i) * NTP + tbase + tt];
        }
#pragma unroll
        for (int r = 0; r < 8; r++) {
            int idx = tid + 128 * r;
            int tt = idx >> 5, kk = idx & 31;
            bsS2[tt][kk] = g_basis2[(tbase + tt) * 32 + kk];
        }
        __syncthreads();
#pragma unroll 8
        for (int tt = 0; tt < TCA; tt++) {
            ulonglong2 a01 = *(const ulonglong2*)&bsS2[tt][k0];
            ulonglong2 a23 = *(const ulonglong2*)&bsS2[tt][k0 + 2];
            ulonglong2 bv  = *(const ulonglong2*)&vsT[tt][i0];
            fma2(acc[0][0], a01.x, bv.x); fma2(acc[0][1], a01.x, bv.y);
            fma2(acc[1][0], a01.y, bv.x); fma2(acc[1][1], a01.y, bv.y);
            fma2(acc[2][0], a23.x, bv.x); fma2(acc[2][1], a23.x, bv.y);
            fma2(acc[3][0], a23.y, bv.x); fma2(acc[3][1], a23.y, bv.y);
        }
        __syncthreads();
    }
    float* fp = g_fpart + (size_t)(s * BB + b) * WW * 32;
#pragma unroll
    for (int ak = 0; ak < 4; ak++)
#pragma unroll
        for (int p = 0; p < 2; p++) {
            float2 f = up2(acc[ak][p]);
            fp[(i0 + 2 * p) * 32 + k0 + ak]     = f.x;
            fp[(i0 + 2 * p + 1) * 32 + k0 + ak] = f.y;
        }
}

// mode mixing + irfft-coefficient fold -> dup'd coefficients
__global__ void __launch_bounds__(1024) k_mix(const float* __restrict__ kr,
                                              const float* __restrict__ ki) {
    __shared__ float Fs[WW][32];
    int b = blockIdx.x, tid = threadIdx.x;
#pragma unroll
    for (int r = 0; r < 2; r++) {
        int idx = tid + 1024 * r;
        float s0 = 0.f, s1 = 0.f;
#pragma unroll
        for (int s = 0; s < NSPL; s += 2) {
            s0 += g_fpart[(size_t)(s * BB + b) * WW * 32 + idx];
            s1 += g_fpart[(size_t)((s + 1) * BB + b) * WW * 32 + idx];
        }
        ((float*)Fs)[idx] = s0 + s1;
    }
    __syncthreads();
    int k = tid & 15, o = tid >> 4;
    float ck = (k == 0) ? (1.0f / (float)NTR) : (2.0f / (float)NTR);
    float pr = 0.f, pi = 0.f;
#pragma unroll 4
    for (int i = 0; i < WW; i++) {
        float fr = Fs[i][k];
        float fs = Fs[i][NMD + k];
        float krv = __ldg(&kr[(i * WW + o) * NMD + k]);
        float kiv = __ldg(&ki[(i * WW + o) * NMD + k]);
        pr = fmaf(fr, krv, fmaf(fs, kiv, pr));
        pi = fmaf(fr, kiv, fmaf(-fs, krv, pi));
    }
    g_ab2[(b * 32 + k) * WW + o]       = pk2(ck * pr);
    g_ab2[(b * 32 + NMD + k) * WW + o] = pk2(-ck * pi);
}

// fused inverse DFT + channel conv + bias + GELU (f32x2, 72KB dyn smem)
__global__ void __launch_bounds__(128) k_pt(int src,
                                            const u64* __restrict__ cw2,
                                            const float* __restrict__ cb) {
    const float* __restrict__ vin  = src ? g_v1 : g_v0;
    float* __restrict__       vout = src ? g_v0 : g_v1;
    extern __shared__ __align__(16) u64 sm[];
    u64* vsP  = sm;          // [64 i][32 tp]   2048
    u64* cw2s = sm + 2048;   // [64 i][64 o]    4096
    u64* bsP  = sm + 6144;   // [32 kk][32 tp]  1024
    u64* ab2s = sm + 7168;   // [32 kk][64 o]   2048
    int b = blockIdx.x;
    int t0 = blockIdx.y * 64;
    int tid = threadIdx.x;
#pragma unroll
    for (int r = 0; r < 16; r++) {
        int idx = tid + 128 * r;
        int i = idx >> 5, tp = idx & 31;
        vsP[idx] = *(const u64*)&vin[(b * WW + i) * NTP + t0 + tp * 2];
    }
#pragma unroll
    for (int r = 0; r < 32; r++) {
        int idx = tid + 128 * r;
        cw2s[idx] = cw2[idx];
    }
#pragma unroll
    for (int r = 0; r < 8; r++) {
        int idx = tid + 128 * r;
        int kk = idx >> 5, tp = idx & 31;
        bsP[idx] = *(const u64*)&g_basisT[kk * NTP + t0 + tp * 2];
    }
#pragma unroll
    for (int r = 0; r < 16; r++) {
        int idx = tid + 128 * r;
        ab2s[idx] = g_ab2[b * 2048 + idx];
    }
    __syncthreads();

    int to = tid & 15, tt = tid >> 4;
    int o0 = to * 4, tp0 = tt * 4;
    u64 acc[4][4];
#pragma unroll
    for (int a = 0; a < 4; a++) {
        u64 c = pk2(__ldg(&cb[o0 + a]));
        acc[a][0] = c; acc[a][1] = c; acc[a][2] = c; acc[a][3] = c;
    }
#pragma unroll 8
    for (int i = 0; i < WW; i++) {
        ulonglong2 a01 = *(const ulonglong2*)&cw2s[i * 64 + o0];
        ulonglong2 a23 = *(const ulonglong2*)&cw2s[i * 64 + o0 + 2];
        ulonglong2 b01 = *(const ulonglong2*)&vsP[i * 32 + tp0];
        ulonglong2 b23 = *(const ulonglong2*)&vsP[i * 32 + tp0 + 2];
        FMA2_4x4(a01, a23, b01, b23);
    }
#pragma unroll 8
    for (int kk = 0; kk < 32; kk++) {
        ulonglong2 a01 = *(const ulonglong2*)&ab2s[kk * 64 + o0];
        ulonglong2 a23 = *(const ulonglong2*)&ab2s[kk * 64 + o0 + 2];
        ulonglong2 b01 = *(const ulonglong2*)&bsP[kk * 32 + tp0];
        ulonglong2 b23 = *(const ulonglong2*)&bsP[kk * 32 + tp0 + 2];
        FMA2_4x4(a01, a23, b01, b23);
    }
#pragma unroll
    for (int a = 0; a < 4; a++) {
        float2 f0 = up2(acc[a][0]);
        float2 f1 = up2(acc[a][1]);
        float2 f2 = up2(acc[a][2]);
        float2 f3 = up2(acc[a][3]);
        float g[8] = { gelu_f(f0.x), gelu_f(f0.y), gelu_f(f1.x), gelu_f(f1.y),
                       gelu_f(f2.x), gelu_f(f2.y), gelu_f(f3.x), gelu_f(f3.y) };
        int tb = t0 + tp0 * 2;
        size_t base = (size_t)(b * WW + o0 + a) * NTP + tb;
        if (tb + 7 < NTR) {
            *(float4*)&vout[base]     = make_float4(g[0], g[1], g[2], g[3]);
            *(float4*)&vout[base + 4] = make_float4(g[4], g[5], g[6], g[7]);
        } else {
#pragma unroll
            for (int q = 0; q < 8; q++)
                if (tb + q < NTR) vout[base + q] = g[q];
        }
    }
}

// final projection (f32x2): out = gelu(v @ pw1 + b1) @ pw2 + b2
__global__ void __launch_bounds__(128) k_proj(const float* __restrict__ pw1,
                                              const float* __restrict__ pb1,
                                              const float* __restrict__ pw2,
                                              const float* __restrict__ pb2,
                                              float* __restrict__ out) {
    __shared__ __align__(16) u64 vs2[WW * 32];    // [i][t] dup'd, 16KB
    __shared__ __align__(16) u64 pw1P[WW * 64];   // [i][jp], 32KB
    int b = blockIdx.x;
    int t0 = blockIdx.y * 32;
    int tid = threadIdx.x;
#pragma unroll
    for (int r = 0; r < 16; r++) {
        int idx = tid + 128 * r;
        int i = idx >> 5, t = idx & 31;
        vs2[idx] = pk2(g_v1[(b * WW + i) * NTP + t0 + t]);
    }
#pragma unroll
    for (int r = 0; r < 32; r++) {
        int idx = tid + 128 * r;
        pw1P[idx] = ((const u64*)pw1)[idx];
    }
    __syncthreads();

    int tj = tid & 15, tt = tid >> 4;
    int j0p = tj * 4, tr0 = tt * 4;
    u64 acc[4][4] = {};
#pragma unroll 8
    for (int i = 0; i < WW; i++) {
        ulonglong2 a01 = *(const ulonglong2*)&vs2[i * 32 + tr0];
        ulonglong2 a23 = *(const ulonglong2*)&vs2[i * 32 + tr0 + 2];
        ulonglong2 b01 = *(const ulonglong2*)&pw1P[i * 64 + j0p];
        ulonglong2 b23 = *(const ulonglong2*)&pw1P[i * 64 + j0p + 2];
        FMA2_4x4(a01, a23, b01, b23);
    }
    float s[4] = {};
#pragma unroll
    for (int p = 0; p < 4; p++) {
        int j = tj * 8 + 2 * p;
        float b1l = __ldg(&pb1[j]),  b1h = __ldg(&pb1[j + 1]);
        float w2l = __ldg(&pw2[j]),  w2h = __ldg(&pw2[j + 1]);
#pragma unroll
        for (int a = 0; a < 4; a++) {
            float2 f = up2(acc[a][p]);
            s[a] = fmaf(gelu_f(f.x + b1l), w2l, s[a]);
            s[a] = fmaf(gelu_f(f.y + b1h), w2h, s[a]);
        }
    }
#pragma unroll
    for (int m = 8; m >= 1; m >>= 1)
#pragma unroll
        for (int a = 0; a < 4; a++)
            s[a] += __shfl_xor_sync(0xffffffffu, s[a], m);
    if (tj == 0) {
        float b2 = __ldg(&pb2[0]);
#pragma unroll
        for (int a = 0; a < 4; a++)
            out[b * FNSEQ + t0 + tr0 + a] = s[a] + b2;
    }
}

extern "C" void kernel_launch(void* const* d_in, const int* in_sizes, int n_in,
                              void* d_out, int out_size) {
    const float* x   = (const float*)d_in[0];
    const float* lw  = (const float*)d_in[1];
    const float* lb  = (const float*)d_in[2];
    const float* kr  = (const float*)d_in[3];
    const float* ki  = (const float*)d_in[4];
    const float* cw  = (const float*)d_in[5];
    const float* cb  = (const float*)d_in[6];
    const float* pw1 = (const float*)d_in[7];
    const float* pb1 = (const float*)d_in[8];
    const float* pw2 = (const float*)d_in[9];
    const float* pb2 = (const float*)d_in[10];
    float* out = (float*)d_out;

    static int attr_done = 0;
    if (!attr_done) {
        cudaFuncSetAttribute(k_pt, cudaFuncAttributeMaxDynamicSharedMemorySize, 73728);
        attr_done = 1;
    }

    u64* cw2_dev = nullptr;
    cudaGetSymbolAddress((void**)&cw2_dev, g_cw2);

    k_basis<<<(NTP + 127) / 128, 128>>>();
    k_prep<<<(5 * WW * WW + 127) / 128, 128>>>(cw);
    k_lift<<<dim3(BB, (NTP + 127) / 128), 128>>>(x, lw, lb);
    for (int l = 0; l < 5; l++) {
        int src = l & 1;
        k_fwd<<<dim3(BB, NSPL), 128>>>(src);
        k_mix<<<BB, 1024>>>(kr + l * WW * WW * NMD, ki + l * WW * WW * NMD);
        k_pt<<<dim3(BB, NTP / 64), 128, 73728>>>(src, cw2_dev + l * WW * WW,
                                                 cb + l * WW);
    }
    k_proj<<<dim3(BB, FNSEQ / 32), 128>>>(pw1, pb1, pw2, pb2, out);
}

// round 9
// speedup vs baseline: 1.0124x; 1.0124x over previous
#include <cuda_runtime.h>
#include <cuda_bf16.h>
#include <cstdint>

#define BB    64
#define WW    64
#define FNSEQ 8192
#define NTR   8201
#define NTP   8320
#define NMD   16
#define NSPL  10
#define TRG   832
#define TCA   32

__device__ float g_v0[BB * WW * NTP];
__device__ float g_v1[BB * WW * NTP];
__device__ float g_basis[NTP * 32];            // fp32 [t][kk] for k_fwd
__device__ uint32_t g_bh2[NTP * 16];           // bf16-pair basis hi [t][kp]
__device__ uint32_t g_bl2[NTP * 16];           // lo
__device__ uint32_t g_cwh2[5 * 2048];          // bf16-pair conv w hi [l][o][ip]
__device__ uint32_t g_cwl2[5 * 2048];          // lo
__device__ __nv_bfloat16 g_abh[BB * WW * 32];  // [b][o][kk] hi
__device__ __nv_bfloat16 g_abl[BB * WW * 32];  // lo
__device__ float g_fpart[NSPL * BB * WW * 32];

__device__ __forceinline__ float gelu_f(float x) {
    return 0.5f * x * (1.0f + erff(x * 0.70710678118654752f));
}
__device__ __forceinline__ uint32_t smem_u32(const void* p) {
    uint32_t a;
    asm("{ .reg .u64 t; cvta.to.shared.u64 t, %1; cvt.u32.u64 %0, t; }" : "=r"(a) : "l"(p));
    return a;
}
__device__ __forceinline__ uint32_t pack_bf(__nv_bfloat16 a, __nv_bfloat16 b) {
    return (uint32_t)__bfloat16_as_ushort(a) | ((uint32_t)__bfloat16_as_ushort(b) << 16);
}
__device__ __forceinline__ uint32_t pack_hl(float v0, float v1, uint32_t& lo) {
    __nv_bfloat16 h0 = __float2bfloat16(v0), h1 = __float2bfloat16(v1);
    lo = pack_bf(__float2bfloat16(v0 - __bfloat162float(h0)),
                 __float2bfloat16(v1 - __bfloat162float(h1)));
    return pack_bf(h0, h1);
}
__device__ __forceinline__ void ldmx4(uint32_t* d, uint32_t addr) {
    asm volatile("ldmatrix.sync.aligned.m8n8.x4.shared.b16 {%0,%1,%2,%3}, [%4];"
                 : "=r"(d[0]), "=r"(d[1]), "=r"(d[2]), "=r"(d[3]) : "r"(addr));
}
__device__ __forceinline__ void ldmx2(uint32_t* d, uint32_t addr) {
    asm volatile("ldmatrix.sync.aligned.m8n8.x2.shared.b16 {%0,%1}, [%2];"
                 : "=r"(d[0]), "=r"(d[1]) : "r"(addr));
}
__device__ __forceinline__ void mma_bf16(float* c, const uint32_t* a, const uint32_t* b) {
    asm volatile(
        "mma.sync.aligned.m16n8k16.row.col.f32.bf16.bf16.f32 "
        "{%0,%1,%2,%3}, {%4,%5,%6,%7}, {%8,%9}, {%0,%1,%2,%3};"
        : "+f"(c[0]), "+f"(c[1]), "+f"(c[2]), "+f"(c[3])
        : "r"(a[0]), "r"(a[1]), "r"(a[2]), "r"(a[3]), "r"(b[0]), "r"(b[1]));
}

#define FMA16(A, B)                             \
    acc[0][0] = fmaf((A).x, (B).x, acc[0][0]);  \
    acc[0][1] = fmaf((A).x, (B).y, acc[0][1]);  \
    acc[0][2] = fmaf((A).x, (B).z, acc[0][2]);  \
    acc[0][3] = fmaf((A).x, (B).w, acc[0][3]);  \
    acc[1][0] = fmaf((A).y, (B).x, acc[1][0]);  \
    acc[1][1] = fmaf((A).y, (B).y, acc[1][1]);  \
    acc[1][2] = fmaf((A).y, (B).z, acc[1][2]);  \
    acc[1][3] = fmaf((A).y, (B).w, acc[1][3]);  \
    acc[2][0] = fmaf((A).z, (B).x, acc[2][0]);  \
    acc[2][1] = fmaf((A).z, (B).y, acc[2][1]);  \
    acc[2][2] = fmaf((A).z, (B).z, acc[2][2]);  \
    acc[2][3] = fmaf((A).z, (B).w, acc[2][3]);  \
    acc[3][0] = fmaf((A).w, (B).x, acc[3][0]);  \
    acc[3][1] = fmaf((A).w, (B).y, acc[3][1]);  \
    acc[3][2] = fmaf((A).w, (B).z, acc[3][2]);  \
    acc[3][3] = fmaf((A).w, (B).w, acc[3][3]);

__global__ void k_basis() {
    int t = blockIdx.x * 128 + threadIdx.x;
    if (t >= NTP) return;
    float vals[32];
#pragma unroll
    for (int k = 0; k < NMD; k++) {
        int r = (k * t) % NTR;
        float ang = (float)((double)r * (6.283185307179586 / (double)NTR));
        float s, c;
        sincosf(ang, &s, &c);
        vals[k] = c;
        vals[NMD + k] = s;
        g_basis[t * 32 + k] = c;
        g_basis[t * 32 + NMD + k] = s;
    }
#pragma unroll
    for (int kp = 0; kp < 16; kp++) {
        uint32_t lo;
        g_bh2[t * 16 + kp] = pack_hl(vals[2 * kp], vals[2 * kp + 1], lo);
        g_bl2[t * 16 + kp] = lo;
    }
}

// conv weights -> bf16 hi/lo pairs [l][o][ip]
__global__ void k_prep(const float* __restrict__ cw) {
    int idx = blockIdx.x * 128 + threadIdx.x;   // 5*64*32
    if (idx >= 5 * 64 * 32) return;
    int l = idx >> 11, rem = idx & 2047;
    int o = rem >> 5, ip = rem & 31, i = ip * 2;
    uint32_t lo;
    uint32_t hi = pack_hl(cw[(l * WW + o) * WW + i], cw[(l * WW + o) * WW + i + 1], lo);
    g_cwh2[idx] = hi;
    g_cwl2[idx] = lo;
}

__global__ void k_lift(const float* __restrict__ x,
                       const float* __restrict__ lw,
                       const float* __restrict__ lb) {
    int b = blockIdx.x;
    int t = blockIdx.y * 128 + threadIdx.x;
    if (t >= NTP) return;
    if (t >= NTR) {
#pragma unroll 4
        for (int i = 0; i < WW; i++) g_v1[(b * WW + i) * NTP + t] = 0.0f;
    }
    if (t >= FNSEQ) {
#pragma unroll 4
        for (int i = 0; i < WW; i++) g_v0[(b * WW + i) * NTP + t] = 0.0f;
        return;
    }
    float x0 = x[(b * FNSEQ + t) * 2 + 0];
    float x1 = x[(b * FNSEQ + t) * 2 + 1];
#pragma unroll 4
    for (int i = 0; i < WW; i++) {
        g_v0[(b * WW + i) * NTP + t] =
            fmaf(x0, __ldg(&lw[i]), fmaf(x1, __ldg(&lw[WW + i]), __ldg(&lb[i])));
    }
}

// forward restricted DFT partials: F[b,i,k] over t-split s (scalar, R4)
__global__ void __launch_bounds__(128) k_fwd(int src) {
    const float* __restrict__ vin = src ? g_v1 : g_v0;
    __shared__ __align__(16) float vsT[TCA][WW + 4];
    __shared__ __align__(16) float bsS[TCA][32];
    int b = blockIdx.x, s = blockIdx.y, tid = threadIdx.x;
    int ti = tid & 15, tk = tid >> 4;
    int i0 = ti * 4, k0 = tk * 4;
    float acc[4][4] = {};
    const int tbeg = s * TRG;
    for (int tc = 0; tc < TRG; tc += TCA) {
        int tbase = tbeg + tc;
#pragma unroll
        for (int r = 0; r < 16; r++) {
            int idx = tid + 128 * r;
            int i = idx >> 5, tt = idx & 31;
            vsT[tt][i] = vin[(b * WW + i) * NTP + tbase + tt];
        }
#pragma unroll
        for (int r = 0; r < 2; r++) {
            int idx = tid + 128 * r;
            ((float4*)bsS)[idx] = ((const float4*)(g_basis + tbase * 32))[idx];
        }
        __syncthreads();
#pragma unroll
        for (int tt = 0; tt < TCA; tt++) {
            float4 vv = *(const float4*)&vsT[tt][i0];
            float4 bb = *(const float4*)&bsS[tt][k0];
            FMA16(vv, bb);
        }
        __syncthreads();
    }
    float* fp = g_fpart + (size_t)(s * BB + b) * WW * 32;
#pragma unroll
    for (int a = 0; a < 4; a++)
        *(float4*)&fp[(i0 + a) * 32 + k0] =
            make_float4(acc[a][0], acc[a][1], acc[a][2], acc[a][3]);
}

// mode mixing + irfft fold -> bf16 hi/lo coefficient tables
__global__ void __launch_bounds__(1024) k_mix(const float* __restrict__ kr,
                                              const float* __restrict__ ki) {
    __shared__ float Fs[WW][32];
    int b = blockIdx.x, tid = threadIdx.x;
#pragma unroll
    for (int r = 0; r < 2; r++) {
        int idx = tid + 1024 * r;
        float sum = 0.f;
#pragma unroll
        for (int s = 0; s < NSPL; s++)
            sum += g_fpart[(size_t)(s * BB + b) * WW * 32 + idx];
        ((float*)Fs)[idx] = sum;
    }
    __syncthreads();
    int k = tid & 15, o = tid >> 4;
    float ck = (k == 0) ? (1.0f / (float)NTR) : (2.0f / (float)NTR);
    float pr = 0.f, pi = 0.f;
#pragma unroll 4
    for (int i = 0; i < WW; i++) {
        float fr = Fs[i][k];
        float fs = Fs[i][NMD + k];
        float krv = __ldg(&kr[(i * WW + o) * NMD + k]);
        float kiv = __ldg(&ki[(i * WW + o) * NMD + k]);
        pr = fmaf(fr, krv, fmaf(fs, kiv, pr));
        pi = fmaf(fr, kiv, fmaf(-fs, krv, pi));
    }
    float a_cos = ck * pr, a_sin = -ck * pi;
    int base = ((b << 6) + o) * 32;
    __nv_bfloat16 hc = __float2bfloat16(a_cos);
    __nv_bfloat16 hs = __float2bfloat16(a_sin);
    g_abh[base + k] = hc;
    g_abl[base + k] = __float2bfloat16(a_cos - __bfloat162float(hc));
    g_abh[base + NMD + k] = hs;
    g_abl[base + NMD + k] = __float2bfloat16(a_sin - __bfloat162float(hs));
}

// ---- mma.sync fused layer: D[t,o] = Vcat[t,96] x Wcat[o,96], +bias, GELU ----
// A smem: [128 t][104 k] bf16, hi & lo (cols 0..63 v, 64..95 basis)
// B smem: [64 o][104 k] bf16, hi & lo (cols 0..63 cw, 64..95 ab)
#define KP     104
#define SM_CB  0
#define SM_AH  256
#define SM_AL  (256 + 26624)
#define SM_BH  53504
#define SM_BL  66816
#define SMEM_PT 80128
__global__ void __launch_bounds__(128) k_pt(int src, int l,
                                            const float* __restrict__ cb) {
    const float* __restrict__ vin  = src ? g_v1 : g_v0;
    float* __restrict__       vout = src ? g_v0 : g_v1;
    extern __shared__ __align__(16) char sm[];
    uint32_t smb = smem_u32(sm);
    float* cbS = (float*)(sm + SM_CB);
    float* Csm = (float*)(sm + SM_AH);          // overlay, [64 o][132]
    int b = blockIdx.x;
    int t0 = blockIdx.y * 128;
    int tid = threadIdx.x, wid = tid >> 5, lane = tid & 31;

    if (tid < 64) cbS[tid] = cb[tid];
    // A: v channels (cols 0..63)
#pragma unroll
    for (int r = 0; r < 8; r++) {
        int idx = tid + 128 * r;
        int ip = idx >> 5, tq = idx & 31, i = ip * 2;
        float4 fa = *(const float4*)&vin[(size_t)(b * WW + i) * NTP + t0 + tq * 4];
        float4 fb = *(const float4*)&vin[(size_t)(b * WW + i + 1) * NTP + t0 + tq * 4];
        float va[4] = {fa.x, fa.y, fa.z, fa.w};
        float vb[4] = {fb.x, fb.y, fb.z, fb.w};
#pragma unroll
        for (int q = 0; q < 4; q++) {
            int t = tq * 4 + q;
            uint32_t lo;
            uint32_t hi = pack_hl(va[q], vb[q], lo);
            *(uint32_t*)(sm + SM_AH + (t * KP + i) * 2) = hi;
            *(uint32_t*)(sm + SM_AL + (t * KP + i) * 2) = lo;
        }
    }
    // A: basis (cols 64..95)
#pragma unroll
    for (int r = 0; r < 16; r++) {
        int idx = tid + 128 * r;
        int t = idx >> 4, kp = idx & 15;
        *(uint32_t*)(sm + SM_AH + (t * KP + 64 + 2 * kp) * 2) = g_bh2[(t0 + t) * 16 + kp];
        *(uint32_t*)(sm + SM_AL + (t * KP + 64 + 2 * kp) * 2) = g_bl2[(t0 + t) * 16 + kp];
    }
    // B: conv weights (cols 0..63)
#pragma unroll
    for (int r = 0; r < 16; r++) {
        int idx = tid + 128 * r;
        int o = idx >> 5, ip = idx & 31;
        *(uint32_t*)(sm + SM_BH + (o * KP + 2 * ip) * 2) = g_cwh2[l * 2048 + idx];
        *(uint32_t*)(sm + SM_BL + (o * KP + 2 * ip) * 2) = g_cwl2[l * 2048 + idx];
    }
    // B: ab coefficients (cols 64..95)
#pragma unroll
    for (int r = 0; r < 8; r++) {
        int idx = tid + 128 * r;
        int o = idx >> 4, kp = idx & 15;
        int gi = ((b << 6) + o) * 32 + 2 * kp;
        *(uint32_t*)(sm + SM_BH + (o * KP + 64 + 2 * kp) * 2) =
            *(const uint32_t*)&g_abh[gi];
        *(uint32_t*)(sm + SM_BL + (o * KP + 64 + 2 * kp) * 2) =
            *(const uint32_t*)&g_abl[gi];
    }
    __syncthreads();

    int wT = wid * 32;
    float acc[2][8][4];
#pragma unroll
    for (int mt = 0; mt < 2; mt++)
#pragma unroll
        for (int nt = 0; nt < 8; nt++)
#pragma unroll
            for (int c = 0; c < 4; c++) acc[mt][nt][c] = 0.f;

    uint32_t aoff = ((lane & 15) * KP + (lane >> 4) * 8) * 2;
    uint32_t boff = ((lane & 7) * KP + ((lane >> 3) & 1) * 8) * 2;
#pragma unroll
    for (int kt = 0; kt < 6; kt++) {
        int k0 = kt * 16;
        uint32_t ah[2][4], al[2][4];
#pragma unroll
        for (int mt = 0; mt < 2; mt++) {
            uint32_t base = ((wT + mt * 16) * KP + k0) * 2 + aoff;
            ldmx4(ah[mt], smb + SM_AH + base);
            ldmx4(al[mt], smb + SM_AL + base);
        }
#pragma unroll
        for (int nt = 0; nt < 8; nt++) {
            uint32_t bb = (nt * 8 * KP + k0) * 2 + boff;
            uint32_t bh[2], bl[2];
            ldmx2(bh, smb + SM_BH + bb);
            ldmx2(bl, smb + SM_BL + bb);
#pragma unroll
            for (int mt = 0; mt < 2; mt++) {
                mma_bf16(acc[mt][nt], ah[mt], bh);
                mma_bf16(acc[mt][nt], al[mt], bh);
                mma_bf16(acc[mt][nt], ah[mt], bl);
            }
        }
    }
    __syncthreads();   // all warps done reading A before C overlay

    int cr = lane >> 2, cc = (lane & 3) * 2;
#pragma unroll
    for (int mt = 0; mt < 2; mt++)
#pragma unroll
        for (int nt = 0; nt < 8; nt++) {
            int t = wT + mt * 16 + cr;
            int o = nt * 8 + cc;
            Csm[o * 132 + t]           = acc[mt][nt][0];
            Csm[(o + 1) * 132 + t]     = acc[mt][nt][1];
            Csm[o * 132 + t + 8]       = acc[mt][nt][2];
            Csm[(o + 1) * 132 + t + 8] = acc[mt][nt][3];
        }
    __syncthreads();

#pragma unroll
    for (int r = 0; r < 16; r++) {
        int idx = tid + 128 * r;
        int o = idx >> 5, tq = idx & 31;
        float4 v = *(const float4*)&Csm[o * 132 + tq * 4];
        float bias = cbS[o];
        float4 g;
        g.x = gelu_f(v.x + bias);
        g.y = gelu_f(v.y + bias);
        g.z = gelu_f(v.z + bias);
        g.w = gelu_f(v.w + bias);
        int tg = t0 + tq * 4;
        size_t base = (size_t)(b * WW + o) * NTP + tg;
        if (tg + 3 < NTR) {
            *(float4*)&vout[base] = g;
        } else {
            if (tg + 0 < NTR) vout[base + 0] = g.x;
            if (tg + 1 < NTR) vout[base + 1] = g.y;
            if (tg + 2 < NTR) vout[base + 2] = g.z;
            if (tg + 3 < NTR) vout[base + 3] = g.w;
        }
    }
}

// final projection (scalar, R4): out = gelu(v @ pw1 + b1) @ pw2 + b2
__global__ void __launch_bounds__(256) k_proj(const float* __restrict__ pw1,
                                              const float* __restrict__ pb1,
                                              const float* __restrict__ pw2,
                                              const float* __restrict__ pb2,
                                              float* __restrict__ out) {
    __shared__ __align__(16) float vs[WW][64];
    __shared__ __align__(16) float pw1s[WW][128];
    int b = blockIdx.x;
    int t0 = blockIdx.y * 64;
    int tid = threadIdx.x;
#pragma unroll
    for (int r = 0; r < 4; r++) {
        int idx = tid + 256 * r;
        int i = idx >> 4, tq = idx & 15;
        ((float4*)&vs[i][0])[tq] =
            *(const float4*)&g_v1[(b * WW + i) * NTP + t0 + tq * 4];
    }
#pragma unroll
    for (int r = 0; r < 8; r++) {
        int idx = tid + 256 * r;
        ((float4*)pw1s)[idx] = ((const float4*)pw1)[idx];
    }
    __syncthreads();

    int tj = tid & 15, tt = tid >> 4;
    int j0 = tj * 8, tr0 = tt * 4;
    float acc[4][8] = {};
#pragma unroll 4
    for (int i = 0; i < WW; i++) {
        float4 vv = *(const float4*)&vs[i][tr0];
        float4 p0 = *(const float4*)&pw1s[i][j0];
        float4 p1 = *(const float4*)&pw1s[i][j0 + 4];
        float va[4] = {vv.x, vv.y, vv.z, vv.w};
        float pc[8] = {p0.x, p0.y, p0.z, p0.w, p1.x, p1.y, p1.z, p1.w};
#pragma unroll
        for (int a = 0; a < 4; a++)
#pragma unroll
            for (int c = 0; c < 8; c++)
                acc[a][c] = fmaf(va[a], pc[c], acc[a][c]);
    }
    float s[4] = {};
#pragma unroll
    for (int c = 0; c < 8; c++) {
        float b1 = __ldg(&pb1[j0 + c]);
        float w2 = __ldg(&pw2[j0 + c]);
#pragma unroll
        for (int a = 0; a < 4; a++)
            s[a] = fmaf(gelu_f(acc[a][c] + b1), w2, s[a]);
    }
#pragma unroll
    for (int m = 8; m >= 1; m >>= 1)
#pragma unroll
        for (int a = 0; a < 4; a++)
            s[a] += __shfl_xor_sync(0xffffffffu, s[a], m);
    if (tj == 0) {
        float b2 = __ldg(&pb2[0]);
#pragma unroll
        for (int a = 0; a < 4; a++)
            out[b * FNSEQ + t0 + tr0 + a] = s[a] + b2;
    }
}

extern "C" void kernel_launch(void* const* d_in, const int* in_sizes, int n_in,
                              void* d_out, int out_size) {
    const float* x   = (const float*)d_in[0];
    const float* lw  = (const float*)d_in[1];
    const float* lb  = (const float*)d_in[2];
    const float* kr  = (const float*)d_in[3];
    const float* ki  = (const float*)d_in[4];
    const float* cw  = (const float*)d_in[5];
    const float* cb  = (const float*)d_in[6];
    const float* pw1 = (const float*)d_in[7];
    const float* pb1 = (const float*)d_in[8];
    const float* pw2 = (const float*)d_in[9];
    const float* pb2 = (const float*)d_in[10];
    float* out = (float*)d_out;

    static int attr_done = 0;
    if (!attr_done) {
        cudaFuncSetAttribute(k_pt, cudaFuncAttributeMaxDynamicSharedMemorySize, SMEM_PT);
        attr_done = 1;
    }

    k_basis<<<(NTP + 127) / 128, 128>>>();
    k_prep<<<(5 * 64 * 32 + 127) / 128, 128>>>(cw);
    k_lift<<<dim3(BB, (NTP + 127) / 128), 128>>>(x, lw, lb);
    for (int l = 0; l < 5; l++) {
        int src = l & 1;
        k_fwd<<<dim3(BB, NSPL), 128>>>(src);
        k_mix<<<BB, 1024>>>(kr + l * WW * WW * NMD, ki + l * WW * WW * NMD);
        k_pt<<<dim3(BB, NTP / 128), 128, SMEM_PT>>>(src, l, cb + l * WW);
    }
    k_proj<<<dim3(BB, FNSEQ / 64), 256>>>(pw1, pb1, pw2, pb2, out);
}

// round 11
// speedup vs baseline: 1.7682x; 1.7465x over previous
#include <cuda_runtime.h>
#include <cuda_bf16.h>
#include <cstdint>

#define BB    64
#define WW    64
#define FNSEQ 8192
#define NTR   8201
#define NTP   8320
#define NMD   16
#define NSPL  20
#define TRG   416
#define TCA   32

__device__ float g_v0[BB * WW * NTP];
__device__ float g_v1[BB * WW * NTP];
__device__ float g_basis[NTP * 32];            // fp32 [t][kk] for k_fwd
__device__ uint32_t g_bh2[NTP * 16];           // bf16-pair basis hi [t][kp]
__device__ uint32_t g_bl2[NTP * 16];           // lo
__device__ uint32_t g_cwh2[5 * 2048];          // bf16-pair conv w hi [l][o][ip]
__device__ uint32_t g_cwl2[5 * 2048];          // lo
__device__ __nv_bfloat16 g_abh[BB * WW * 32];  // [b][o][kk] hi
__device__ __nv_bfloat16 g_abl[BB * WW * 32];  // lo
__device__ float g_fpart[NSPL * BB * WW * 32];

__device__ __forceinline__ float gelu_f(float x) {
    return 0.5f * x * (1.0f + erff(x * 0.70710678118654752f));
}
__device__ __forceinline__ uint32_t smem_u32(const void* p) {
    uint32_t a;
    asm("{ .reg .u64 t; cvta.to.shared.u64 t, %1; cvt.u32.u64 %0, t; }" : "=r"(a) : "l"(p));
    return a;
}
__device__ __forceinline__ uint32_t pack_bf(__nv_bfloat16 a, __nv_bfloat16 b) {
    return (uint32_t)__bfloat16_as_ushort(a) | ((uint32_t)__bfloat16_as_ushort(b) << 16);
}
__device__ __forceinline__ uint32_t pack_hl(float v0, float v1, uint32_t& lo) {
    __nv_bfloat16 h0 = __float2bfloat16(v0), h1 = __float2bfloat16(v1);
    lo = pack_bf(__float2bfloat16(v0 - __bfloat162float(h0)),
                 __float2bfloat16(v1 - __bfloat162float(h1)));
    return pack_bf(h0, h1);
}
__device__ __forceinline__ void ldmx4(uint32_t* d, uint32_t addr) {
    asm volatile("ldmatrix.sync.aligned.m8n8.x4.shared.b16 {%0,%1,%2,%3}, [%4];"
                 : "=r"(d[0]), "=r"(d[1]), "=r"(d[2]), "=r"(d[3]) : "r"(addr));
}
__device__ __forceinline__ void ldmx2(uint32_t* d, uint32_t addr) {
    asm volatile("ldmatrix.sync.aligned.m8n8.x2.shared.b16 {%0,%1}, [%2];"
                 : "=r"(d[0]), "=r"(d[1]) : "r"(addr));
}
__device__ __forceinline__ void mma_bf16(float* c, const uint32_t* a, const uint32_t* b) {
    asm volatile(
        "mma.sync.aligned.m16n8k16.row.col.f32.bf16.bf16.f32 "
        "{%0,%1,%2,%3}, {%4,%5,%6,%7}, {%8,%9}, {%0,%1,%2,%3};"
        : "+f"(c[0]), "+f"(c[1]), "+f"(c[2]), "+f"(c[3])
        : "r"(a[0]), "r"(a[1]), "r"(a[2]), "r"(a[3]), "r"(b[0]), "r"(b[1]));
}

#define FMA16(A, B)                             \
    acc[0][0] = fmaf((A).x, (B).x, acc[0][0]);  \
    acc[0][1] = fmaf((A).x, (B).y, acc[0][1]);  \
    acc[0][2] = fmaf((A).x, (B).z, acc[0][2]);  \
    acc[0][3] = fmaf((A).x, (B).w, acc[0][3]);  \
    acc[1][0] = fmaf((A).y, (B).x, acc[1][0]);  \
    acc[1][1] = fmaf((A).y, (B).y, acc[1][1]);  \
    acc[1][2] = fmaf((A).y, (B).z, acc[1][2]);  \
    acc[1][3] = fmaf((A).y, (B).w, acc[1][3]);  \
    acc[2][0] = fmaf((A).z, (B).x, acc[2][0]);  \
    acc[2][1] = fmaf((A).z, (B).y, acc[2][1]);  \
    acc[2][2] = fmaf((A).z, (B).z, acc[2][2]);  \
    acc[2][3] = fmaf((A).z, (B).w, acc[2][3]);  \
    acc[3][0] = fmaf((A).w, (B).x, acc[3][0]);  \
    acc[3][1] = fmaf((A).w, (B).y, acc[3][1]);  \
    acc[3][2] = fmaf((A).w, (B).z, acc[3][2]);  \
    acc[3][3] = fmaf((A).w, (B).w, acc[3][3]);

__global__ void k_basis() {
    int t = blockIdx.x * 128 + threadIdx.x;
    if (t >= NTP) return;
    float vals[32];
#pragma unroll
    for (int k = 0; k < NMD; k++) {
        int r = (k * t) % NTR;
        float ang = (float)((double)r * (6.283185307179586 / (double)NTR));
        float s, c;
        sincosf(ang, &s, &c);
        vals[k] = c;
        vals[NMD + k] = s;
        g_basis[t * 32 + k] = c;
        g_basis[t * 32 + NMD + k] = s;
    }
#pragma unroll
    for (int kp = 0; kp < 16; kp++) {
        uint32_t lo;
        g_bh2[t * 16 + kp] = pack_hl(vals[2 * kp], vals[2 * kp + 1], lo);
        g_bl2[t * 16 + kp] = lo;
    }
}

__global__ void k_prep(const float* __restrict__ cw) {
    int idx = blockIdx.x * 128 + threadIdx.x;   // 5*64*32
    if (idx >= 5 * 64 * 32) return;
    int l = idx >> 11, rem = idx & 2047;
    int o = rem >> 5, ip = rem & 31, i = ip * 2;
    uint32_t lo;
    uint32_t hi = pack_hl(cw[(l * WW + o) * WW + i], cw[(l * WW + o) * WW + i + 1], lo);
    g_cwh2[idx] = hi;
    g_cwl2[idx] = lo;
}

__global__ void k_lift(const float* __restrict__ x,
                       const float* __restrict__ lw,
                       const float* __restrict__ lb) {
    int b = blockIdx.x;
    int t = blockIdx.y * 128 + threadIdx.x;
    if (t >= NTP) return;
    if (t >= NTR) {
#pragma unroll 4
        for (int i = 0; i < WW; i++) g_v1[(b * WW + i) * NTP + t] = 0.0f;
    }
    if (t >= FNSEQ) {
#pragma unroll 4
        for (int i = 0; i < WW; i++) g_v0[(b * WW + i) * NTP + t] = 0.0f;
        return;
    }
    float x0 = x[(b * FNSEQ + t) * 2 + 0];
    float x1 = x[(b * FNSEQ + t) * 2 + 1];
#pragma unroll 4
    for (int i = 0; i < WW; i++) {
        g_v0[(b * WW + i) * NTP + t] =
            fmaf(x0, __ldg(&lw[i]), fmaf(x1, __ldg(&lw[WW + i]), __ldg(&lb[i])));
    }
}

// forward restricted DFT partials over t-split s (scalar; NSPL=20 for occupancy)
__global__ void __launch_bounds__(128) k_fwd(int src) {
    const float* __restrict__ vin = src ? g_v1 : g_v0;
    __shared__ __align__(16) float vsT[TCA][WW + 4];
    __shared__ __align__(16) float bsS[TCA][32];
    int b = blockIdx.x, s = blockIdx.y, tid = threadIdx.x;
    int ti = tid & 15, tk = tid >> 4;
    int i0 = ti * 4, k0 = tk * 4;
    float acc[4][4] = {};
    const int tbeg = s * TRG;
    for (int tc = 0; tc < TRG; tc += TCA) {
        int tbase = tbeg + tc;
#pragma unroll
        for (int r = 0; r < 16; r++) {
            int idx = tid + 128 * r;
            int i = idx >> 5, tt = idx & 31;
            vsT[tt][i] = vin[(b * WW + i) * NTP + tbase + tt];
        }
#pragma unroll
        for (int r = 0; r < 2; r++) {
            int idx = tid + 128 * r;
            ((float4*)bsS)[idx] = ((const float4*)(g_basis + tbase * 32))[idx];
        }
        __syncthreads();
#pragma unroll
        for (int tt = 0; tt < TCA; tt++) {
            float4 vv = *(const float4*)&vsT[tt][i0];
            float4 bb = *(const float4*)&bsS[tt][k0];
            FMA16(vv, bb);
        }
        __syncthreads();
    }
    float* fp = g_fpart + (size_t)(s * BB + b) * WW * 32;
#pragma unroll
    for (int a = 0; a < 4; a++)
        *(float4*)&fp[(i0 + a) * 32 + k0] =
            make_float4(acc[a][0], acc[a][1], acc[a][2], acc[a][3]);
}

// mode mixing + irfft fold -> bf16 hi/lo coefficient tables
__global__ void __launch_bounds__(1024) k_mix(const float* __restrict__ kr,
                                              const float* __restrict__ ki) {
    __shared__ float Fs[WW][32];
    int b = blockIdx.x, tid = threadIdx.x;
#pragma unroll
    for (int r = 0; r < 2; r++) {
        int idx = tid + 1024 * r;
        float sum = 0.f;
#pragma unroll
        for (int s = 0; s < NSPL; s++)
            sum += g_fpart[(size_t)(s * BB + b) * WW * 32 + idx];
        ((float*)Fs)[idx] = sum;
    }
    __syncthreads();
    int k = tid & 15, o = tid >> 4;
    float ck = (k == 0) ? (1.0f / (float)NTR) : (2.0f / (float)NTR);
    float pr = 0.f, pi = 0.f;
#pragma unroll 4
    for (int i = 0; i < WW; i++) {
        float fr = Fs[i][k];
        float fs = Fs[i][NMD + k];
        float krv = __ldg(&kr[(i * WW + o) * NMD + k]);
        float kiv = __ldg(&ki[(i * WW + o) * NMD + k]);
        pr = fmaf(fr, krv, fmaf(fs, kiv, pr));
        pi = fmaf(fr, kiv, fmaf(-fs, krv, pi));
    }
    float a_cos = ck * pr, a_sin = -ck * pi;
    int base = ((b << 6) + o) * 32;
    __nv_bfloat16 hc = __float2bfloat16(a_cos);
    __nv_bfloat16 hs = __float2bfloat16(a_sin);
    g_abh[base + k] = hc;
    g_abl[base + k] = __float2bfloat16(a_cos - __bfloat162float(hc));
    g_abh[base + NMD + k] = hs;
    g_abl[base + NMD + k] = __float2bfloat16(a_sin - __bfloat162float(hs));
}

// ---- mma.sync fused layer v2: 256 threads, warp tile 32t x 32o ----
#define KP     104
#define SM_CB  0
#define SM_AH  256
#define SM_AL  (256 + 26624)
#define SM_BH  53504
#define SM_BL  66816
#define SMEM_PT 80128
__global__ void __launch_bounds__(256) k_pt(int src, int l,
                                            const float* __restrict__ cb) {
    const float* __restrict__ vin  = src ? g_v1 : g_v0;
    float* __restrict__       vout = src ? g_v0 : g_v1;
    extern __shared__ __align__(16) char sm[];
    uint32_t smb = smem_u32(sm);
    float* cbS = (float*)(sm + SM_CB);
    float* Csm = (float*)(sm + SM_AH);          // overlay, [64 o][132]
    int b = blockIdx.x;
    int t0 = blockIdx.y * 128;
    int tid = threadIdx.x, wid = tid >> 5, lane = tid & 31;

    if (tid < 64) cbS[tid] = cb[tid];
    // A: v channels (cols 0..63)
#pragma unroll
    for (int r = 0; r < 4; r++) {
        int idx = tid + 256 * r;
        int ip = idx >> 5, tq = idx & 31, i = ip * 2;
        float4 fa = *(const float4*)&vin[(size_t)(b * WW + i) * NTP + t0 + tq * 4];
        float4 fb = *(const float4*)&vin[(size_t)(b * WW + i + 1) * NTP + t0 + tq * 4];
        float va[4] = {fa.x, fa.y, fa.z, fa.w};
        float vb[4] = {fb.x, fb.y, fb.z, fb.w};
#pragma unroll
        for (int q = 0; q < 4; q++) {
            int t = tq * 4 + q;
            uint32_t lo;
            uint32_t hi = pack_hl(va[q], vb[q], lo);
            *(uint32_t*)(sm + SM_AH + (t * KP + i) * 2) = hi;
            *(uint32_t*)(sm + SM_AL + (t * KP + i) * 2) = lo;
        }
    }
    // A: basis (cols 64..95)
#pragma unroll
    for (int r = 0; r < 8; r++) {
        int idx = tid + 256 * r;
        int t = idx >> 4, kp = idx & 15;
        *(uint32_t*)(sm + SM_AH + (t * KP + 64 + 2 * kp) * 2) = g_bh2[(t0 + t) * 16 + kp];
        *(uint32_t*)(sm + SM_AL + (t * KP + 64 + 2 * kp) * 2) = g_bl2[(t0 + t) * 16 + kp];
    }
    // B: conv weights (cols 0..63)
#pragma unroll
    for (int r = 0; r < 8; r++) {
        int idx = tid + 256 * r;
        int o = idx >> 5, ip = idx & 31;
        *(uint32_t*)(sm + SM_BH + (o * KP + 2 * ip) * 2) = g_cwh2[l * 2048 + idx];
        *(uint32_t*)(sm + SM_BL + (o * KP + 2 * ip) * 2) = g_cwl2[l * 2048 + idx];
    }
    // B: ab coefficients (cols 64..95)
#pragma unroll
    for (int r = 0; r < 4; r++) {
        int idx = tid + 256 * r;
        int o = idx >> 4, kp = idx & 15;
        int gi = ((b << 6) + o) * 32 + 2 * kp;
        *(uint32_t*)(sm + SM_BH + (o * KP + 64 + 2 * kp) * 2) =
            *(const uint32_t*)&g_abh[gi];
        *(uint32_t*)(sm + SM_BL + (o * KP + 64 + 2 * kp) * 2) =
            *(const uint32_t*)&g_abl[gi];
    }
    __syncthreads();

    int wT = (wid >> 1) * 32;      // t base of this warp (4 quadrants of 32)
    int oG = (wid & 1) * 32;       // o base (2 halves of 32)
    float acc[2][4][4];
#pragma unroll
    for (int mt = 0; mt < 2; mt++)
#pragma unroll
        for (int nt = 0; nt < 4; nt++)
#pragma unroll
            for (int c = 0; c < 4; c++) acc[mt][nt][c] = 0.f;

    uint32_t aoff = ((lane & 15) * KP + (lane >> 4) * 8) * 2;
    uint32_t boff = ((lane & 7) * KP + ((lane >> 3) & 1) * 8) * 2;
#pragma unroll
    for (int kt = 0; kt < 6; kt++) {
        int k0 = kt * 16;
        uint32_t ah[2][4], al[2][4];
#pragma unroll
        for (int mt = 0; mt < 2; mt++) {
            uint32_t base = ((wT + mt * 16) * KP + k0) * 2 + aoff;
            ldmx4(ah[mt], smb + SM_AH + base);
            ldmx4(al[mt], smb + SM_AL + base);
        }
#pragma unroll
        for (int nt = 0; nt < 4; nt++) {
            uint32_t bb = ((oG + nt * 8) * KP + k0) * 2 + boff;
            uint32_t bh[2], bl[2];
            ldmx2(bh, smb + SM_BH + bb);
            ldmx2(bl, smb + SM_BL + bb);
#pragma unroll
            for (int mt = 0; mt < 2; mt++) {
                mma_bf16(acc[mt][nt], ah[mt], bh);
                mma_bf16(acc[mt][nt], al[mt], bh);
                mma_bf16(acc[mt][nt], ah[mt], bl);
            }
        }
    }
    __syncthreads();   // all warps done reading A before C overlay

    int cr = lane >> 2, cc = (lane & 3) * 2;
#pragma unroll
    for (int mt = 0; mt < 2; mt++)
#pragma unroll
        for (int nt = 0; nt < 4; nt++) {
            int t = wT + mt * 16 + cr;
            int o = oG + nt * 8 + cc;
            Csm[o * 132 + t]           = acc[mt][nt][0];
            Csm[(o + 1) * 132 + t]     = acc[mt][nt][1];
            Csm[o * 132 + t + 8]       = acc[mt][nt][2];
            Csm[(o + 1) * 132 + t + 8] = acc[mt][nt][3];
        }
    __syncthreads();

#pragma unroll
    for (int r = 0; r < 8; r++) {
        int idx = tid + 256 * r;
        int o = idx >> 5, tq = idx & 31;
        float4 v = *(const float4*)&Csm[o * 132 + tq * 4];
        float bias = cbS[o];
        float4 g;
        g.x = gelu_f(v.x + bias);
        g.y = gelu_f(v.y + bias);
        g.z = gelu_f(v.z + bias);
        g.w = gelu_f(v.w + bias);
        int tg = t0 + tq * 4;
        size_t base = (size_t)(b * WW + o) * NTP + tg;
        if (tg + 3 < NTR) {
            *(float4*)&vout[base] = g;
        } else {
            if (tg + 0 < NTR) vout[base + 0] = g.x;
            if (tg + 1 < NTR) vout[base + 1] = g.y;
            if (tg + 2 < NTR) vout[base + 2] = g.z;
            if (tg + 3 < NTR) vout[base + 3] = g.w;
        }
    }
}

// final projection (scalar): out = gelu(v @ pw1 + b1) @ pw2 + b2
__global__ void __launch_bounds__(256) k_proj(const float* __restrict__ pw1,
                                              const float* __restrict__ pb1,
                                              const float* __restrict__ pw2,
                                              const float* __restrict__ pb2,
                                              float* __restrict__ out) {
    __shared__ __align__(16) float vs[WW][64];
    __shared__ __align__(16) float pw1s[WW][128];
    int b = blockIdx.x;
    int t0 = blockIdx.y * 64;
    int tid = threadIdx.x;
#pragma unroll
    for (int r = 0; r < 4; r++) {
        int idx = tid + 256 * r;
        int i = idx >> 4, tq = idx & 15;
        ((float4*)&vs[i][0])[tq] =
            *(const float4*)&g_v1[(b * WW + i) * NTP + t0 + tq * 4];
    }
#pragma unroll
    for (int r = 0; r < 8; r++) {
        int idx = tid + 256 * r;
        ((float4*)pw1s)[idx] = ((const float4*)pw1)[idx];
    }
    __syncthreads();

    int tj = tid & 15, tt = tid >> 4;
    int j0 = tj * 8, tr0 = tt * 4;
    float acc[4][8] = {};
#pragma unroll 4
    for (int i = 0; i < WW; i++) {
        float4 vv = *(const float4*)&vs[i][tr0];
        float4 p0 = *(const float4*)&pw1s[i][j0];
        float4 p1 = *(const float4*)&pw1s[i][j0 + 4];
        float va[4] = {vv.x, vv.y, vv.z, vv.w};
        float pc[8] = {p0.x, p0.y, p0.z, p0.w, p1.x, p1.y, p1.z, p1.w};
#pragma unroll
        for (int a = 0; a < 4; a++)
#pragma unroll
            for (int c = 0; c < 8; c++)
                acc[a][c] = fmaf(va[a], pc[c], acc[a][c]);
    }
    float s[4] = {};
#pragma unroll
    for (int c = 0; c < 8; c++) {
        float b1 = __ldg(&pb1[j0 + c]);
        float w2 = __ldg(&pw2[j0 + c]);
#pragma unroll
        for (int a = 0; a < 4; a++)
            s[a] = fmaf(gelu_f(acc[a][c] + b1), w2, s[a]);
    }
#pragma unroll
    for (int m = 8; m >= 1; m >>= 1)
#pragma unroll
        for (int a = 0; a < 4; a++)
            s[a] += __shfl_xor_sync(0xffffffffu, s[a], m);
    if (tj == 0) {
        float b2 = __ldg(&pb2[0]);
#pragma unroll
        for (int a = 0; a < 4; a++)
            out[b * FNSEQ + t0 + tr0 + a] = s[a] + b2;
    }
}

extern "C" void kernel_launch(void* const* d_in, const int* in_sizes, int n_in,
                              void* d_out, int out_size) {
    const float* x   = (const float*)d_in[0];
    const float* lw  = (const float*)d_in[1];
    const float* lb  = (const float*)d_in[2];
    const float* kr  = (const float*)d_in[3];
    const float* ki  = (const float*)d_in[4];
    const float* cw  = (const float*)d_in[5];
    const float* cb  = (const float*)d_in[6];
    const float* pw1 = (const float*)d_in[7];
    const float* pb1 = (const float*)d_in[8];
    const float* pw2 = (const float*)d_in[9];
    const float* pb2 = (const float*)d_in[10];
    float* out = (float*)d_out;

    static int attr_done = 0;
    if (!attr_done) {
        cudaFuncSetAttribute(k_pt, cudaFuncAttributeMaxDynamicSharedMemorySize, SMEM_PT);
        attr_done = 1;
    }

    k_basis<<<(NTP + 127) / 128, 128>>>();
    k_prep<<<(5 * 64 * 32 + 127) / 128, 128>>>(cw);
    k_lift<<<dim3(BB, (NTP + 127) / 128), 128>>>(x, lw, lb);
    for (int l = 0; l < 5; l++) {
        int src = l & 1;
        k_fwd<<<dim3(BB, NSPL), 128>>>(src);
        k_mix<<<BB, 1024>>>(kr + l * WW * WW * NMD, ki + l * WW * WW * NMD);
        k_pt<<<dim3(BB, NTP / 128), 256, SMEM_PT>>>(src, l, cb + l * WW);
    }
    k_proj<<<dim3(BB, FNSEQ / 64), 256>>>(pw1, pb1, pw2, pb2, out);
}

// round 12
// speedup vs baseline: 1.8955x; 1.0720x over previous
#include <cuda_runtime.h>
#include <cuda_bf16.h>
#include <cstdint>

#define BB    64
#define WW    64
#define FNSEQ 8192
#define NTR   8201
#define NTP   8320
#define NMD   16
#define NSPL  65
#define TRGF  128
#define TCA   32

__device__ float g_v0[BB * WW * NTP];
__device__ float g_v1[BB * WW * NTP];
__device__ float g_basis[NTP * 32];            // fp32 [t][kk] for scalar k_fwd
__device__ uint32_t g_bh2[NTP * 16];           // bf16-pair basis hi [t][kp] (A layout)
__device__ uint32_t g_bl2[NTP * 16];           // lo
__device__ __nv_bfloat16 g_bthT[32 * NTP];     // bf16 basis hi [k][t] (B layout)
__device__ __nv_bfloat16 g_btlT[32 * NTP];     // lo
__device__ uint32_t g_cwh2[5 * 2048];          // bf16-pair conv w hi [l][o][ip]
__device__ uint32_t g_cwl2[5 * 2048];          // lo
__device__ __nv_bfloat16 g_abh[BB * WW * 32];  // [b][o][kk] hi
__device__ __nv_bfloat16 g_abl[BB * WW * 32];  // lo
__device__ float g_fpart[NSPL * BB * WW * 32];

__device__ __forceinline__ float gelu_f(float x) {
    return 0.5f * x * (1.0f + erff(x * 0.70710678118654752f));
}
__device__ __forceinline__ uint32_t smem_u32(const void* p) {
    uint32_t a;
    asm("{ .reg .u64 t; cvta.to.shared.u64 t, %1; cvt.u32.u64 %0, t; }" : "=r"(a) : "l"(p));
    return a;
}
__device__ __forceinline__ uint32_t pack_bf(__nv_bfloat16 a, __nv_bfloat16 b) {
    return (uint32_t)__bfloat16_as_ushort(a) | ((uint32_t)__bfloat16_as_ushort(b) << 16);
}
__device__ __forceinline__ uint32_t pack_hl(float v0, float v1, uint32_t& lo) {
    __nv_bfloat16 h0 = __float2bfloat16(v0), h1 = __float2bfloat16(v1);
    lo = pack_bf(__float2bfloat16(v0 - __bfloat162float(h0)),
                 __float2bfloat16(v1 - __bfloat162float(h1)));
    return pack_bf(h0, h1);
}
__device__ __forceinline__ void ldmx4(uint32_t* d, uint32_t addr) {
    asm volatile("ldmatrix.sync.aligned.m8n8.x4.shared.b16 {%0,%1,%2,%3}, [%4];"
                 : "=r"(d[0]), "=r"(d[1]), "=r"(d[2]), "=r"(d[3]) : "r"(addr));
}
__device__ __forceinline__ void ldmx2(uint32_t* d, uint32_t addr) {
    asm volatile("ldmatrix.sync.aligned.m8n8.x2.shared.b16 {%0,%1}, [%2];"
                 : "=r"(d[0]), "=r"(d[1]) : "r"(addr));
}
__device__ __forceinline__ void mma_bf16(float* c, const uint32_t* a, const uint32_t* b) {
    asm volatile(
        "mma.sync.aligned.m16n8k16.row.col.f32.bf16.bf16.f32 "
        "{%0,%1,%2,%3}, {%4,%5,%6,%7}, {%8,%9}, {%0,%1,%2,%3};"
        : "+f"(c[0]), "+f"(c[1]), "+f"(c[2]), "+f"(c[3])
        : "r"(a[0]), "r"(a[1]), "r"(a[2]), "r"(a[3]), "r"(b[0]), "r"(b[1]));
}

#define FMA16(A, B)                             \
    acc[0][0] = fmaf((A).x, (B).x, acc[0][0]);  \
    acc[0][1] = fmaf((A).x, (B).y, acc[0][1]);  \
    acc[0][2] = fmaf((A).x, (B).z, acc[0][2]);  \
    acc[0][3] = fmaf((A).x, (B).w, acc[0][3]);  \
    acc[1][0] = fmaf((A).y, (B).x, acc[1][0]);  \
    acc[1][1] = fmaf((A).y, (B).y, acc[1][1]);  \
    acc[1][2] = fmaf((A).y, (B).z, acc[1][2]);  \
    acc[1][3] = fmaf((A).y, (B).w, acc[1][3]);  \
    acc[2][0] = fmaf((A).z, (B).x, acc[2][0]);  \
    acc[2][1] = fmaf((A).z, (B).y, acc[2][1]);  \
    acc[2][2] = fmaf((A).z, (B).z, acc[2][2]);  \
    acc[2][3] = fmaf((A).z, (B).w, acc[2][3]);  \
    acc[3][0] = fmaf((A).w, (B).x, acc[3][0]);  \
    acc[3][1] = fmaf((A).w, (B).y, acc[3][1]);  \
    acc[3][2] = fmaf((A).w, (B).z, acc[3][2]);  \
    acc[3][3] = fmaf((A).w, (B).w, acc[3][3]);

__global__ void k_basis() {
    int t = blockIdx.x * 128 + threadIdx.x;
    if (t >= NTP) return;
    float vals[32];
#pragma unroll
    for (int k = 0; k < NMD; k++) {
        int r = (k * t) % NTR;
        float ang = (float)((double)r * (6.283185307179586 / (double)NTR));
        float s, c;
        sincosf(ang, &s, &c);
        vals[k] = c;
        vals[NMD + k] = s;
        g_basis[t * 32 + k] = c;
        g_basis[t * 32 + NMD + k] = s;
    }
#pragma unroll
    for (int kp = 0; kp < 16; kp++) {
        uint32_t lo;
        g_bh2[t * 16 + kp] = pack_hl(vals[2 * kp], vals[2 * kp + 1], lo);
        g_bl2[t * 16 + kp] = lo;
    }
#pragma unroll
    for (int k = 0; k < 32; k++) {
        float v = vals[k];
        __nv_bfloat16 h = __float2bfloat16(v);
        g_bthT[k * NTP + t] = h;
        g_btlT[k * NTP + t] = __float2bfloat16(v - __bfloat162float(h));
    }
}

__global__ void k_prep(const float* __restrict__ cw) {
    int idx = blockIdx.x * 128 + threadIdx.x;   // 5*64*32
    if (idx >= 5 * 64 * 32) return;
    int l = idx >> 11, rem = idx & 2047;
    int o = rem >> 5, ip = rem & 31, i = ip * 2;
    uint32_t lo;
    uint32_t hi = pack_hl(cw[(l * WW + o) * WW + i], cw[(l * WW + o) * WW + i + 1], lo);
    g_cwh2[idx] = hi;
    g_cwl2[idx] = lo;
}

__global__ void k_lift(const float* __restrict__ x,
                       const float* __restrict__ lw,
                       const float* __restrict__ lb) {
    int b = blockIdx.x;
    int t = blockIdx.y * 128 + threadIdx.x;
    if (t >= NTP) return;
    if (t >= NTR) {
#pragma unroll 4
        for (int i = 0; i < WW; i++) g_v1[(b * WW + i) * NTP + t] = 0.0f;
    }
    if (t >= FNSEQ) {
#pragma unroll 4
        for (int i = 0; i < WW; i++) g_v0[(b * WW + i) * NTP + t] = 0.0f;
        return;
    }
    float x0 = x[(b * FNSEQ + t) * 2 + 0];
    float x1 = x[(b * FNSEQ + t) * 2 + 1];
#pragma unroll 4
    for (int i = 0; i < WW; i++) {
        g_v0[(b * WW + i) * NTP + t] =
            fmaf(x0, __ldg(&lw[i]), fmaf(x1, __ldg(&lw[WW + i]), __ldg(&lb[i])));
    }
}

// forward restricted DFT partials (scalar, layer 0 only): 65 splits of 128 t
__global__ void __launch_bounds__(128) k_fwd() {
    const float* __restrict__ vin = g_v0;
    __shared__ __align__(16) float vsT[TCA][WW + 4];
    __shared__ __align__(16) float bsS[TCA][32];
    int b = blockIdx.x, s = blockIdx.y, tid = threadIdx.x;
    int ti = tid & 15, tk = tid >> 4;
    int i0 = ti * 4, k0 = tk * 4;
    float acc[4][4] = {};
    const int tbeg = s * TRGF;
    for (int tc = 0; tc < TRGF; tc += TCA) {
        int tbase = tbeg + tc;
#pragma unroll
        for (int r = 0; r < 16; r++) {
            int idx = tid + 128 * r;
            int i = idx >> 5, tt = idx & 31;
            vsT[tt][i] = vin[(b * WW + i) * NTP + tbase + tt];
        }
#pragma unroll
        for (int r = 0; r < 2; r++) {
            int idx = tid + 128 * r;
            ((float4*)bsS)[idx] = ((const float4*)(g_basis + tbase * 32))[idx];
        }
        __syncthreads();
#pragma unroll
        for (int tt = 0; tt < TCA; tt++) {
            float4 vv = *(const float4*)&vsT[tt][i0];
            float4 bb = *(const float4*)&bsS[tt][k0];
            FMA16(vv, bb);
        }
        __syncthreads();
    }
    float* fp = g_fpart + (size_t)(s * BB + b) * WW * 32;
#pragma unroll
    for (int a = 0; a < 4; a++)
        *(float4*)&fp[(i0 + a) * 32 + k0] =
            make_float4(acc[a][0], acc[a][1], acc[a][2], acc[a][3]);
}

// mode mixing + irfft fold -> bf16 hi/lo coefficient tables (sums 65 partials)
__global__ void __launch_bounds__(1024) k_mix(const float* __restrict__ kr,
                                              const float* __restrict__ ki) {
    __shared__ float Fs[WW][32];
    int b = blockIdx.x, tid = threadIdx.x;
#pragma unroll
    for (int r = 0; r < 2; r++) {
        int idx = tid + 1024 * r;
        float sum = 0.f;
        for (int s = 0; s < NSPL; s++)
            sum += g_fpart[(size_t)(s * BB + b) * WW * 32 + idx];
        ((float*)Fs)[idx] = sum;
    }
    __syncthreads();
    int k = tid & 15, o = tid >> 4;
    float ck = (k == 0) ? (1.0f / (float)NTR) : (2.0f / (float)NTR);
    float pr = 0.f, pi = 0.f;
#pragma unroll 4
    for (int i = 0; i < WW; i++) {
        float fr = Fs[i][k];
        float fs = Fs[i][NMD + k];
        float krv = __ldg(&kr[(i * WW + o) * NMD + k]);
        float kiv = __ldg(&ki[(i * WW + o) * NMD + k]);
        pr = fmaf(fr, krv, fmaf(fs, kiv, pr));
        pi = fmaf(fr, kiv, fmaf(-fs, krv, pi));
    }
    float a_cos = ck * pr, a_sin = -ck * pi;
    int base = ((b << 6) + o) * 32;
    __nv_bfloat16 hc = __float2bfloat16(a_cos);
    __nv_bfloat16 hs = __float2bfloat16(a_sin);
    g_abh[base + k] = hc;
    g_abl[base + k] = __float2bfloat16(a_cos - __bfloat162float(hc));
    g_abh[base + NMD + k] = hs;
    g_abl[base + NMD + k] = __float2bfloat16(a_sin - __bfloat162float(hs));
}

// ---- mma.sync fused layer + fused next-layer forward-DFT epilogue ----
#define KP      104
#define SM_CB   0
#define SM_AH   256
#define SM_AL   (256 + 26624)
#define SM_BH   53504
#define SM_BL   66816
#define SM_GH   53504
#define SM_GL   62720
#define SM_BASH 71936
#define SM_BASL 76544
#define SMEM_PT 81152
__global__ void __launch_bounds__(256, 2) k_pt(int src, int l, int do_dft,
                                               const float* __restrict__ cb) {
    const float* __restrict__ vin  = src ? g_v1 : g_v0;
    float* __restrict__       vout = src ? g_v0 : g_v1;
    extern __shared__ __align__(16) char sm[];
    uint32_t smb = smem_u32(sm);
    float* cbS = (float*)(sm + SM_CB);
    float* Csm = (float*)(sm + SM_AH);          // overlay, [64 o][132]
    int b = blockIdx.x;
    int t0 = blockIdx.y * 128;
    int tid = threadIdx.x, wid = tid >> 5, lane = tid & 31;

    if (tid < 64) cbS[tid] = cb[tid];
    // A: v channels (cols 0..63)
#pragma unroll
    for (int r = 0; r < 4; r++) {
        int idx = tid + 256 * r;
        int ip = idx >> 5, tq = idx & 31, i = ip * 2;
        float4 fa = *(const float4*)&vin[(size_t)(b * WW + i) * NTP + t0 + tq * 4];
        float4 fb = *(const float4*)&vin[(size_t)(b * WW + i + 1) * NTP + t0 + tq * 4];
        float va[4] = {fa.x, fa.y, fa.z, fa.w};
        float vb[4] = {fb.x, fb.y, fb.z, fb.w};
#pragma unroll
        for (int q = 0; q < 4; q++) {
            int t = tq * 4 + q;
            uint32_t lo;
            uint32_t hi = pack_hl(va[q], vb[q], lo);
            *(uint32_t*)(sm + SM_AH + (t * KP + i) * 2) = hi;
            *(uint32_t*)(sm + SM_AL + (t * KP + i) * 2) = lo;
        }
    }
    // A: basis (cols 64..95)
#pragma unroll
    for (int r = 0; r < 8; r++) {
        int idx = tid + 256 * r;
        int t = idx >> 4, kp = idx & 15;
        *(uint32_t*)(sm + SM_AH + (t * KP + 64 + 2 * kp) * 2) = g_bh2[(t0 + t) * 16 + kp];
        *(uint32_t*)(sm + SM_AL + (t * KP + 64 + 2 * kp) * 2) = g_bl2[(t0 + t) * 16 + kp];
    }
    // B: conv weights (cols 0..63)
#pragma unroll
    for (int r = 0; r < 8; r++) {
        int idx = tid + 256 * r;
        int o = idx >> 5, ip = idx & 31;
        *(uint32_t*)(sm + SM_BH + (o * KP + 2 * ip) * 2) = g_cwh2[l * 2048 + idx];
        *(uint32_t*)(sm + SM_BL + (o * KP + 2 * ip) * 2) = g_cwl2[l * 2048 + idx];
    }
    // B: ab coefficients (cols 64..95)
#pragma unroll
    for (int r = 0; r < 4; r++) {
        int idx = tid + 256 * r;
        int o = idx >> 4, kp = idx & 15;
        int gi = ((b << 6) + o) * 32 + 2 * kp;
        *(uint32_t*)(sm + SM_BH + (o * KP + 64 + 2 * kp) * 2) =
            *(const uint32_t*)&g_abh[gi];
        *(uint32_t*)(sm + SM_BL + (o * KP + 64 + 2 * kp) * 2) =
            *(const uint32_t*)&g_abl[gi];
    }
    __syncthreads();

    int wT = (wid >> 1) * 32;
    int oG = (wid & 1) * 32;
    float acc[2][4][4];
#pragma unroll
    for (int mt = 0; mt < 2; mt++)
#pragma unroll
        for (int nt = 0; nt < 4; nt++)
#pragma unroll
            for (int c = 0; c < 4; c++) acc[mt][nt][c] = 0.f;

    uint32_t aoff = ((lane & 15) * KP + (lane >> 4) * 8) * 2;
    uint32_t boff = ((lane & 7) * KP + ((lane >> 3) & 1) * 8) * 2;
#pragma unroll
    for (int kt = 0; kt < 6; kt++) {
        int k0 = kt * 16;
        uint32_t ah[2][4], al[2][4];
#pragma unroll
        for (int mt = 0; mt < 2; mt++) {
            uint32_t base = ((wT + mt * 16) * KP + k0) * 2 + aoff;
            ldmx4(ah[mt], smb + SM_AH + base);
            ldmx4(al[mt], smb + SM_AL + base);
        }
#pragma unroll
        for (int nt = 0; nt < 4; nt++) {
            uint32_t bb = ((oG + nt * 8) * KP + k0) * 2 + boff;
            uint32_t bh[2], bl[2];
            ldmx2(bh, smb + SM_BH + bb);
            ldmx2(bl, smb + SM_BL + bb);
#pragma unroll
            for (int mt = 0; mt < 2; mt++) {
                mma_bf16(acc[mt][nt], ah[mt], bh);
                mma_bf16(acc[mt][nt], al[mt], bh);
                mma_bf16(acc[mt][nt], ah[mt], bl);
            }
        }
    }
    __syncthreads();

    int cr = lane >> 2, cc = (lane & 3) * 2;
#pragma unroll
    for (int mt = 0; mt < 2; mt++)
#pragma unroll
        for (int nt = 0; nt < 4; nt++) {
            int t = wT + mt * 16 + cr;
            int o = oG + nt * 8 + cc;
            Csm[o * 132 + t]           = acc[mt][nt][0];
            Csm[(o + 1) * 132 + t]     = acc[mt][nt][1];
            Csm[o * 132 + t + 8]       = acc[mt][nt][2];
            Csm[(o + 1) * 132 + t + 8] = acc[mt][nt][3];
        }
    __syncthreads();

    // GELU + store to gmem, and write gelu'd values back to Csm for the DFT
#pragma unroll
    for (int r = 0; r < 8; r++) {
        int idx = tid + 256 * r;
        int o = idx >> 5, tq = idx & 31;
        float4 v = *(const float4*)&Csm[o * 132 + tq * 4];
        float bias = cbS[o];
        float4 g;
        g.x = gelu_f(v.x + bias);
        g.y = gelu_f(v.y + bias);
        g.z = gelu_f(v.z + bias);
        g.w = gelu_f(v.w + bias);
        int tg = t0 + tq * 4;
        size_t base = (size_t)(b * WW + o) * NTP + tg;
        if (tg + 3 < NTR) {
            *(float4*)&vout[base] = g;
        } else {
            if (tg + 0 < NTR) vout[base + 0] = g.x;
            if (tg + 1 < NTR) vout[base + 1] = g.y;
            if (tg + 2 < NTR) vout[base + 2] = g.z;
            if (tg + 3 < NTR) vout[base + 3] = g.w;
        }
        *(float4*)&Csm[o * 132 + tq * 4] = g;
    }

    if (!do_dft) return;
    __syncthreads();

    // ---- fused forward-DFT partial for the NEXT layer ----
    // F[o,k] = sum_t G[o,t] * basis[k,t] over this CTA's 128-t chunk
    int s = blockIdx.y;
    int wo = (wid >> 1) * 16;   // o-group
    int wk = (wid & 1) * 16;    // k-mode group
    float facc[2][4] = {};
    uint32_t aoff2 = ((lane & 15) * 72 + (lane >> 4) * 8) * 2;
    uint32_t boff2 = ((lane & 7) * 72 + ((lane >> 3) & 1) * 8) * 2;
#pragma unroll
    for (int h = 0; h < 2; h++) {
        int th0 = h * 64;
        // G tiles [64 o][72] bf16 hi/lo (zero beyond NTR)
#pragma unroll
        for (int r = 0; r < 8; r++) {
            int idx = tid + 256 * r;
            int o = idx >> 5, tp = idx & 31;
            int t = th0 + tp * 2;
            float g0 = Csm[o * 132 + t];
            float g1 = Csm[o * 132 + t + 1];
            if (t0 + t >= NTR) g0 = 0.f;
            if (t0 + t + 1 >= NTR) g1 = 0.f;
            uint32_t lo;
            uint32_t hi = pack_hl(g0, g1, lo);
            *(uint32_t*)(sm + SM_GH + (o * 72 + tp * 2) * 2) = hi;
            *(uint32_t*)(sm + SM_GL + (o * 72 + tp * 2) * 2) = lo;
        }
        // basis tiles [32 k][72] bf16 hi/lo
#pragma unroll
        for (int r = 0; r < 4; r++) {
            int idx = tid + 256 * r;
            int k = idx >> 5, tp = idx & 31;
            int tg = t0 + th0 + tp * 2;
            *(uint32_t*)(sm + SM_BASH + (k * 72 + tp * 2) * 2) =
                *(const uint32_t*)&g_bthT[k * NTP + tg];
            *(uint32_t*)(sm + SM_BASL + (k * 72 + tp * 2) * 2) =
                *(const uint32_t*)&g_btlT[k * NTP + tg];
        }
        __syncthreads();
#pragma unroll
        for (int kt = 0; kt < 4; kt++) {
            uint32_t abase = (wo * 72 + kt * 16) * 2 + aoff2;
            uint32_t gh[4], gl[4];
            ldmx4(gh, smb + SM_GH + abase);
            ldmx4(gl, smb + SM_GL + abase);
#pragma unroll
            for (int nt = 0; nt < 2; nt++) {
                uint32_t bbase = ((wk + nt * 8) * 72 + kt * 16) * 2 + boff2;
                uint32_t bh[2], bl[2];
                ldmx2(bh, smb + SM_BASH + bbase);
                ldmx2(bl, smb + SM_BASL + bbase);
                mma_bf16(facc[nt], gh, bh);
                mma_bf16(facc[nt], gl, bh);
                mma_bf16(facc[nt], gh, bl);
            }
        }
        __syncthreads();
    }
    float* fp = g_fpart + (size_t)(s * BB + b) * WW * 32;
#pragma unroll
    for (int nt = 0; nt < 2; nt++) {
        int k = wk + nt * 8 + cc;
        *(float2*)&fp[(wo + cr) * 32 + k]     = make_float2(facc[nt][0], facc[nt][1]);
        *(float2*)&fp[(wo + cr + 8) * 32 + k] = make_float2(facc[nt][2], facc[nt][3]);
    }
}

// final projection (scalar): out = gelu(v @ pw1 + b1) @ pw2 + b2
__global__ void __launch_bounds__(256) k_proj(const float* __restrict__ pw1,
                                              const float* __restrict__ pb1,
                                              const float* __restrict__ pw2,
                                              const float* __restrict__ pb2,
                                              float* __restrict__ out) {
    __shared__ __align__(16) float vs[WW][64];
    __shared__ __align__(16) float pw1s[WW][128];
    int b = blockIdx.x;
    int t0 = blockIdx.y * 64;
    int tid = threadIdx.x;
#pragma unroll
    for (int r = 0; r < 4; r++) {
        int idx = tid + 256 * r;
        int i = idx >> 4, tq = idx & 15;
        ((float4*)&vs[i][0])[tq] =
            *(const float4*)&g_v1[(b * WW + i) * NTP + t0 + tq * 4];
    }
#pragma unroll
    for (int r = 0; r < 8; r++) {
        int idx = tid + 256 * r;
        ((float4*)pw1s)[idx] = ((const float4*)pw1)[idx];
    }
    __syncthreads();

    int tj = tid & 15, tt = tid >> 4;
    int j0 = tj * 8, tr0 = tt * 4;
    float acc[4][8] = {};
#pragma unroll 4
    for (int i = 0; i < WW; i++) {
        float4 vv = *(const float4*)&vs[i][tr0];
        float4 p0 = *(const float4*)&pw1s[i][j0];
        float4 p1 = *(const float4*)&pw1s[i][j0 + 4];
        float va[4] = {vv.x, vv.y, vv.z, vv.w};
        float pc[8] = {p0.x, p0.y, p0.z, p0.w, p1.x, p1.y, p1.z, p1.w};
#pragma unroll
        for (int a = 0; a < 4; a++)
#pragma unroll
            for (int c = 0; c < 8; c++)
                acc[a][c] = fmaf(va[a], pc[c], acc[a][c]);
    }
    float s[4] = {};
#pragma unroll
    for (int c = 0; c < 8; c++) {
        float b1 = __ldg(&pb1[j0 + c]);
        float w2 = __ldg(&pw2[j0 + c]);
#pragma unroll
        for (int a = 0; a < 4; a++)
            s[a] = fmaf(gelu_f(acc[a][c] + b1), w2, s[a]);
    }
#pragma unroll
    for (int m = 8; m >= 1; m >>= 1)
#pragma unroll
        for (int a = 0; a < 4; a++)
            s[a] += __shfl_xor_sync(0xffffffffu, s[a], m);
    if (tj == 0) {
        float b2 = __ldg(&pb2[0]);
#pragma unroll
        for (int a = 0; a < 4; a++)
            out[b * FNSEQ + t0 + tr0 + a] = s[a] + b2;
    }
}

extern "C" void kernel_launch(void* const* d_in, const int* in_sizes, int n_in,
                              void* d_out, int out_size) {
    const float* x   = (const float*)d_in[0];
    const float* lw  = (const float*)d_in[1];
    const float* lb  = (const float*)d_in[2];
    const float* kr  = (const float*)d_in[3];
    const float* ki  = (const float*)d_in[4];
    const float* cw  = (const float*)d_in[5];
    const float* cb  = (const float*)d_in[6];
    const float* pw1 = (const float*)d_in[7];
    const float* pb1 = (const float*)d_in[8];
    const float* pw2 = (const float*)d_in[9];
    const float* pb2 = (const float*)d_in[10];
    float* out = (float*)d_out;

    static int attr_done = 0;
    if (!attr_done) {
        cudaFuncSetAttribute(k_pt, cudaFuncAttributeMaxDynamicSharedMemorySize, SMEM_PT);
        attr_done = 1;
    }

    k_basis<<<(NTP + 127) / 128, 128>>>();
    k_prep<<<(5 * 64 * 32 + 127) / 128, 128>>>(cw);
    k_lift<<<dim3(BB, (NTP + 127) / 128), 128>>>(x, lw, lb);
    k_fwd<<<dim3(BB, NSPL), 128>>>();                       // layer 0 forward DFT
    for (int l = 0; l < 5; l++) {
        int src = l & 1;
        k_mix<<<BB, 1024>>>(kr + l * WW * WW * NMD, ki + l * WW * WW * NMD);
        k_pt<<<dim3(BB, NTP / 128), 256, SMEM_PT>>>(src, l, (l < 4) ? 1 : 0,
                                                    cb + l * WW);
    }
    k_proj<<<dim3(BB, FNSEQ / 64), 256>>>(pw1, pb1, pw2, pb2, out);
}

// round 14
// speedup vs baseline: 2.1049x; 1.1104x over previous
#include <cuda_runtime.h>
#include <cuda_bf16.h>
#include <cstdint>

#define BB    64
#define WW    64
#define FNSEQ 8192
#define NTR   8201
#define NTP   8320
#define NMD   16
#define NSPL  65
#define TRGF  128
#define TCA   32

__device__ float g_v0[BB * WW * NTP];
__device__ float g_v1[BB * WW * NTP];
__device__ float g_basis[NTP * 32];            // fp32 [t][kk] for scalar k_fwd
__device__ uint32_t g_bh2[NTP * 16];           // bf16-pair basis hi [t][kp] (A layout)
__device__ uint32_t g_bl2[NTP * 16];           // lo
__device__ __nv_bfloat16 g_bthT[32 * NTP];     // bf16 basis hi [k][t] (B layout)
__device__ __nv_bfloat16 g_btlT[32 * NTP];     // lo
__device__ uint32_t g_cwh2[5 * 2048];          // bf16-pair conv w hi [l][o][ip]
__device__ uint32_t g_cwl2[5 * 2048];          // lo
__device__ uint32_t g_pw1h2[128 * 32];         // bf16-pair proj_w1 hi [j][ip]
__device__ uint32_t g_pw1l2[128 * 32];         // lo
__device__ __nv_bfloat16 g_abh[BB * WW * 32];  // [b][o][kk] hi
__device__ __nv_bfloat16 g_abl[BB * WW * 32];  // lo
__device__ float g_fpart[NSPL * BB * WW * 32];

__device__ __forceinline__ float gelu_f(float x) {
    return 0.5f * x * (1.0f + erff(x * 0.70710678118654752f));
}
__device__ __forceinline__ uint32_t smem_u32(const void* p) {
    uint32_t a;
    asm("{ .reg .u64 t; cvta.to.shared.u64 t, %1; cvt.u32.u64 %0, t; }" : "=r"(a) : "l"(p));
    return a;
}
__device__ __forceinline__ uint32_t pack_bf(__nv_bfloat16 a, __nv_bfloat16 b) {
    return (uint32_t)__bfloat16_as_ushort(a) | ((uint32_t)__bfloat16_as_ushort(b) << 16);
}
__device__ __forceinline__ uint32_t pack_hl(float v0, float v1, uint32_t& lo) {
    __nv_bfloat16 h0 = __float2bfloat16(v0), h1 = __float2bfloat16(v1);
    lo = pack_bf(__float2bfloat16(v0 - __bfloat162float(h0)),
                 __float2bfloat16(v1 - __bfloat162float(h1)));
    return pack_bf(h0, h1);
}
__device__ __forceinline__ void ldmx4(uint32_t* d, uint32_t addr) {
    asm volatile("ldmatrix.sync.aligned.m8n8.x4.shared.b16 {%0,%1,%2,%3}, [%4];"
                 : "=r"(d[0]), "=r"(d[1]), "=r"(d[2]), "=r"(d[3]) : "r"(addr));
}
__device__ __forceinline__ void ldmx2(uint32_t* d, uint32_t addr) {
    asm volatile("ldmatrix.sync.aligned.m8n8.x2.shared.b16 {%0,%1}, [%2];"
                 : "=r"(d[0]), "=r"(d[1]) : "r"(addr));
}
__device__ __forceinline__ void mma_bf16(float* c, const uint32_t* a, const uint32_t* b) {
    asm volatile(
        "mma.sync.aligned.m16n8k16.row.col.f32.bf16.bf16.f32 "
        "{%0,%1,%2,%3}, {%4,%5,%6,%7}, {%8,%9}, {%0,%1,%2,%3};"
        : "+f"(c[0]), "+f"(c[1]), "+f"(c[2]), "+f"(c[3])
        : "r"(a[0]), "r"(a[1]), "r"(a[2]), "r"(a[3]), "r"(b[0]), "r"(b[1]));
}

#define FMA16(A, B)                             \
    acc[0][0] = fmaf((A).x, (B).x, acc[0][0]);  \
    acc[0][1] = fmaf((A).x, (B).y, acc[0][1]);  \
    acc[0][2] = fmaf((A).x, (B).z, acc[0][2]);  \
    acc[0][3] = fmaf((A).x, (B).w, acc[0][3]);  \
    acc[1][0] = fmaf((A).y, (B).x, acc[1][0]);  \
    acc[1][1] = fmaf((A).y, (B).y, acc[1][1]);  \
    acc[1][2] = fmaf((A).y, (B).z, acc[1][2]);  \
    acc[1][3] = fmaf((A).y, (B).w, acc[1][3]);  \
    acc[2][0] = fmaf((A).z, (B).x, acc[2][0]);  \
    acc[2][1] = fmaf((A).z, (B).y, acc[2][1]);  \
    acc[2][2] = fmaf((A).z, (B).z, acc[2][2]);  \
    acc[2][3] = fmaf((A).z, (B).w, acc[2][3]);  \
    acc[3][0] = fmaf((A).w, (B).x, acc[3][0]);  \
    acc[3][1] = fmaf((A).w, (B).y, acc[3][1]);  \
    acc[3][2] = fmaf((A).w, (B).z, acc[3][2]);  \
    acc[3][3] = fmaf((A).w, (B).w, acc[3][3]);

__global__ void k_basis() {
    int t = blockIdx.x * 128 + threadIdx.x;
    if (t >= NTP) return;
    float vals[32];
#pragma unroll
    for (int k = 0; k < NMD; k++) {
        int r = (k * t) % NTR;
        float ang = (float)((double)r * (6.283185307179586 / (double)NTR));
        float s, c;
        sincosf(ang, &s, &c);
        vals[k] = c;
        vals[NMD + k] = s;
        g_basis[t * 32 + k] = c;
        g_basis[t * 32 + NMD + k] = s;
    }
#pragma unroll
    for (int kp = 0; kp < 16; kp++) {
        uint32_t lo;
        g_bh2[t * 16 + kp] = pack_hl(vals[2 * kp], vals[2 * kp + 1], lo);
        g_bl2[t * 16 + kp] = lo;
    }
#pragma unroll
    for (int k = 0; k < 32; k++) {
        float v = vals[k];
        __nv_bfloat16 h = __float2bfloat16(v);
        g_bthT[k * NTP + t] = h;
        g_btlT[k * NTP + t] = __float2bfloat16(v - __bfloat162float(h));
    }
}

__global__ void k_prep(const float* __restrict__ cw) {
    int idx = blockIdx.x * 128 + threadIdx.x;   // 5*64*32
    if (idx >= 5 * 64 * 32) return;
    int l = idx >> 11, rem = idx & 2047;
    int o = rem >> 5, ip = rem & 31, i = ip * 2;
    uint32_t lo;
    uint32_t hi = pack_hl(cw[(l * WW + o) * WW + i], cw[(l * WW + o) * WW + i + 1], lo);
    g_cwh2[idx] = hi;
    g_cwl2[idx] = lo;
}

__global__ void k_prep2(const float* __restrict__ pw1) {
    int idx = blockIdx.x * 128 + threadIdx.x;   // 128*32
    if (idx >= 128 * 32) return;
    int j = idx >> 5, ip = idx & 31, i = ip * 2;
    uint32_t lo;
    uint32_t hi = pack_hl(pw1[i * 128 + j], pw1[(i + 1) * 128 + j], lo);
    g_pw1h2[idx] = hi;
    g_pw1l2[idx] = lo;
}

__global__ void k_lift(const float* __restrict__ x,
                       const float* __restrict__ lw,
                       const float* __restrict__ lb) {
    int b = blockIdx.x;
    int t = blockIdx.y * 128 + threadIdx.x;
    if (t >= NTP) return;
    if (t >= NTR) {
#pragma unroll 4
        for (int i = 0; i < WW; i++) g_v1[(b * WW + i) * NTP + t] = 0.0f;
    }
    if (t >= FNSEQ) {
#pragma unroll 4
        for (int i = 0; i < WW; i++) g_v0[(b * WW + i) * NTP + t] = 0.0f;
        return;
    }
    float x0 = x[(b * FNSEQ + t) * 2 + 0];
    float x1 = x[(b * FNSEQ + t) * 2 + 1];
#pragma unroll 4
    for (int i = 0; i < WW; i++) {
        g_v0[(b * WW + i) * NTP + t] =
            fmaf(x0, __ldg(&lw[i]), fmaf(x1, __ldg(&lw[WW + i]), __ldg(&lb[i])));
    }
}

// forward restricted DFT partials (scalar, layer 0 only): 65 splits of 128 t
__global__ void __launch_bounds__(128) k_fwd() {
    const float* __restrict__ vin = g_v0;
    __shared__ __align__(16) float vsT[TCA][WW + 4];
    __shared__ __align__(16) float bsS[TCA][32];
    int b = blockIdx.x, s = blockIdx.y, tid = threadIdx.x;
    int ti = tid & 15, tk = tid >> 4;
    int i0 = ti * 4, k0 = tk * 4;
    float acc[4][4] = {};
    const int tbeg = s * TRGF;
    for (int tc = 0; tc < TRGF; tc += TCA) {
        int tbase = tbeg + tc;
#pragma unroll
        for (int r = 0; r < 16; r++) {
            int idx = tid + 128 * r;
            int i = idx >> 5, tt = idx & 31;
            vsT[tt][i] = vin[(b * WW + i) * NTP + tbase + tt];
        }
#pragma unroll
        for (int r = 0; r < 2; r++) {
            int idx = tid + 128 * r;
            ((float4*)bsS)[idx] = ((const float4*)(g_basis + tbase * 32))[idx];
        }
        __syncthreads();
#pragma unroll
        for (int tt = 0; tt < TCA; tt++) {
            float4 vv = *(const float4*)&vsT[tt][i0];
            float4 bb = *(const float4*)&bsS[tt][k0];
            FMA16(vv, bb);
        }
        __syncthreads();
    }
    float* fp = g_fpart + (size_t)(s * BB + b) * WW * 32;
#pragma unroll
    for (int a = 0; a < 4; a++)
        *(float4*)&fp[(i0 + a) * 32 + k0] =
            make_float4(acc[a][0], acc[a][1], acc[a][2], acc[a][3]);
}

// mode mixing + irfft fold -> bf16 hi/lo coefficient tables (sums 65 partials)
__global__ void __launch_bounds__(1024) k_mix(const float* __restrict__ kr,
                                              const float* __restrict__ ki) {
    __shared__ float Fs[WW][32];
    int b = blockIdx.x, tid = threadIdx.x;
#pragma unroll
    for (int r = 0; r < 2; r++) {
        int idx = tid + 1024 * r;
        float sum = 0.f;
        for (int s = 0; s < NSPL; s++)
            sum += g_fpart[(size_t)(s * BB + b) * WW * 32 + idx];
        ((float*)Fs)[idx] = sum;
    }
    __syncthreads();
    int k = tid & 15, o = tid >> 4;
    float ck = (k == 0) ? (1.0f / (float)NTR) : (2.0f / (float)NTR);
    float pr = 0.f, pi = 0.f;
#pragma unroll 4
    for (int i = 0; i < WW; i++) {
        float fr = Fs[i][k];
        float fs = Fs[i][NMD + k];
        float krv = __ldg(&kr[(i * WW + o) * NMD + k]);
        float kiv = __ldg(&ki[(i * WW + o) * NMD + k]);
        pr = fmaf(fr, krv, fmaf(fs, kiv, pr));
        pi = fmaf(fr, kiv, fmaf(-fs, krv, pi));
    }
    float a_cos = ck * pr, a_sin = -ck * pi;
    int base = ((b << 6) + o) * 32;
    __nv_bfloat16 hc = __float2bfloat16(a_cos);
    __nv_bfloat16 hs = __float2bfloat16(a_sin);
    g_abh[base + k] = hc;
    g_abl[base + k] = __float2bfloat16(a_cos - __bfloat162float(hc));
    g_abh[base + NMD + k] = hs;
    g_abl[base + NMD + k] = __float2bfloat16(a_sin - __bfloat162float(hs));
}

// ---- mma.sync fused layer + fused next-layer forward-DFT epilogue ----
#define KP      104
#define SM_CB   0
#define SM_AH   256
#define SM_AL   (256 + 26624)
#define SM_BH   53504
#define SM_BL   66816
#define SM_GH   53504
#define SM_GL   62720
#define SM_BASH 71936
#define SM_BASL 76544
#define SMEM_PT 81152
__global__ void __launch_bounds__(256, 2) k_pt(int src, int l, int do_dft,
                                               const float* __restrict__ cb) {
    const float* __restrict__ vin  = src ? g_v1 : g_v0;
    float* __restrict__       vout = src ? g_v0 : g_v1;
    extern __shared__ __align__(16) char sm[];
    uint32_t smb = smem_u32(sm);
    float* cbS = (float*)(sm + SM_CB);
    float* Csm = (float*)(sm + SM_AH);          // overlay, [64 o][132]
    int b = blockIdx.x;
    int t0 = blockIdx.y * 128;
    int tid = threadIdx.x, wid = tid >> 5, lane = tid & 31;

    if (tid < 64) cbS[tid] = cb[tid];
    // A: v channels (cols 0..63)
#pragma unroll
    for (int r = 0; r < 4; r++) {
        int idx = tid + 256 * r;
        int ip = idx >> 5, tq = idx & 31, i = ip * 2;
        float4 fa = *(const float4*)&vin[(size_t)(b * WW + i) * NTP + t0 + tq * 4];
        float4 fb = *(const float4*)&vin[(size_t)(b * WW + i + 1) * NTP + t0 + tq * 4];
        float va[4] = {fa.x, fa.y, fa.z, fa.w};
        float vb[4] = {fb.x, fb.y, fb.z, fb.w};
#pragma unroll
        for (int q = 0; q < 4; q++) {
            int t = tq * 4 + q;
            uint32_t lo;
            uint32_t hi = pack_hl(va[q], vb[q], lo);
            *(uint32_t*)(sm + SM_AH + (t * KP + i) * 2) = hi;
            *(uint32_t*)(sm + SM_AL + (t * KP + i) * 2) = lo;
        }
    }
    // A: basis (cols 64..95)
#pragma unroll
    for (int r = 0; r < 8; r++) {
        int idx = tid + 256 * r;
        int t = idx >> 4, kp = idx & 15;
        *(uint32_t*)(sm + SM_AH + (t * KP + 64 + 2 * kp) * 2) = g_bh2[(t0 + t) * 16 + kp];
        *(uint32_t*)(sm + SM_AL + (t * KP + 64 + 2 * kp) * 2) = g_bl2[(t0 + t) * 16 + kp];
    }
    // B: conv weights (cols 0..63)
#pragma unroll
    for (int r = 0; r < 8; r++) {
        int idx = tid + 256 * r;
        int o = idx >> 5, ip = idx & 31;
        *(uint32_t*)(sm + SM_BH + (o * KP + 2 * ip) * 2) = g_cwh2[l * 2048 + idx];
        *(uint32_t*)(sm + SM_BL + (o * KP + 2 * ip) * 2) = g_cwl2[l * 2048 + idx];
    }
    // B: ab coefficients (cols 64..95)
#pragma unroll
    for (int r = 0; r < 4; r++) {
        int idx = tid + 256 * r;
        int o = idx >> 4, kp = idx & 15;
        int gi = ((b << 6) + o) * 32 + 2 * kp;
        *(uint32_t*)(sm + SM_BH + (o * KP + 64 + 2 * kp) * 2) =
            *(const uint32_t*)&g_abh[gi];
        *(uint32_t*)(sm + SM_BL + (o * KP + 64 + 2 * kp) * 2) =
            *(const uint32_t*)&g_abl[gi];
    }
    __syncthreads();

    int wT = (wid >> 1) * 32;
    int oG = (wid & 1) * 32;
    float acc[2][4][4];
#pragma unroll
    for (int mt = 0; mt < 2; mt++)
#pragma unroll
        for (int nt = 0; nt < 4; nt++)
#pragma unroll
            for (int c = 0; c < 4; c++) acc[mt][nt][c] = 0.f;

    uint32_t aoff = ((lane & 15) * KP + (lane >> 4) * 8) * 2;
    uint32_t boff = ((lane & 7) * KP + ((lane >> 3) & 1) * 8) * 2;
#pragma unroll
    for (int kt = 0; kt < 6; kt++) {
        int k0 = kt * 16;
        uint32_t ah[2][4], al[2][4];
#pragma unroll
        for (int mt = 0; mt < 2; mt++) {
            uint32_t base = ((wT + mt * 16) * KP + k0) * 2 + aoff;
            ldmx4(ah[mt], smb + SM_AH + base);
            ldmx4(al[mt], smb + SM_AL + base);
        }
#pragma unroll
        for (int nt = 0; nt < 4; nt++) {
            uint32_t bb = ((oG + nt * 8) * KP + k0) * 2 + boff;
            uint32_t bh[2], bl[2];
            ldmx2(bh, smb + SM_BH + bb);
            ldmx2(bl, smb + SM_BL + bb);
#pragma unroll
            for (int mt = 0; mt < 2; mt++) {
                mma_bf16(acc[mt][nt], ah[mt], bh);
                mma_bf16(acc[mt][nt], al[mt], bh);
                mma_bf16(acc[mt][nt], ah[mt], bl);
            }
        }
    }
    __syncthreads();

    // bias + GELU in fragments, write gelu'd values to Csm
    int cr = lane >> 2, cc = (lane & 3) * 2;
#pragma unroll
    for (int mt = 0; mt < 2; mt++)
#pragma unroll
        for (int nt = 0; nt < 4; nt++) {
            int t = wT + mt * 16 + cr;
            int o = oG + nt * 8 + cc;
            float b0 = cbS[o], b1v = cbS[o + 1];
            Csm[o * 132 + t]           = gelu_f(acc[mt][nt][0] + b0);
            Csm[(o + 1) * 132 + t]     = gelu_f(acc[mt][nt][1] + b1v);
            Csm[o * 132 + t + 8]       = gelu_f(acc[mt][nt][2] + b0);
            Csm[(o + 1) * 132 + t + 8] = gelu_f(acc[mt][nt][3] + b1v);
        }
    __syncthreads();

    // store to gmem (Csm already gelu'd)
#pragma unroll
    for (int r = 0; r < 8; r++) {
        int idx = tid + 256 * r;
        int o = idx >> 5, tq = idx & 31;
        float4 g = *(const float4*)&Csm[o * 132 + tq * 4];
        int tg = t0 + tq * 4;
        size_t base = (size_t)(b * WW + o) * NTP + tg;
        if (tg + 3 < NTR) {
            *(float4*)&vout[base] = g;
        } else {
            if (tg + 0 < NTR) vout[base + 0] = g.x;
            if (tg + 1 < NTR) vout[base + 1] = g.y;
            if (tg + 2 < NTR) vout[base + 2] = g.z;
            if (tg + 3 < NTR) vout[base + 3] = g.w;
        }
    }

    if (!do_dft) return;
    __syncthreads();

    // ---- fused forward-DFT partial for the NEXT layer ----
    int s = blockIdx.y;
    int wo = (wid >> 1) * 16;
    int wk = (wid & 1) * 16;
    float facc[2][4] = {};
    uint32_t aoff2 = ((lane & 15) * 72 + (lane >> 4) * 8) * 2;
    uint32_t boff2 = ((lane & 7) * 72 + ((lane >> 3) & 1) * 8) * 2;
#pragma unroll
    for (int h = 0; h < 2; h++) {
        int th0 = h * 64;
#pragma unroll
        for (int r = 0; r < 8; r++) {
            int idx = tid + 256 * r;
            int o = idx >> 5, tp = idx & 31;
            int t = th0 + tp * 2;
            float g0 = Csm[o * 132 + t];
            float g1 = Csm[o * 132 + t + 1];
            if (t0 + t >= NTR) g0 = 0.f;
            if (t0 + t + 1 >= NTR) g1 = 0.f;
            uint32_t lo;
            uint32_t hi = pack_hl(g0, g1, lo);
            *(uint32_t*)(sm + SM_GH + (o * 72 + tp * 2) * 2) = hi;
            *(uint32_t*)(sm + SM_GL + (o * 72 + tp * 2) * 2) = lo;
        }
#pragma unroll
        for (int r = 0; r < 4; r++) {
            int idx = tid + 256 * r;
            int k = idx >> 5, tp = idx & 31;
            int tg = t0 + th0 + tp * 2;
            *(uint32_t*)(sm + SM_BASH + (k * 72 + tp * 2) * 2) =
                *(const uint32_t*)&g_bthT[k * NTP + tg];
            *(uint32_t*)(sm + SM_BASL + (k * 72 + tp * 2) * 2) =
                *(const uint32_t*)&g_btlT[k * NTP + tg];
        }
        __syncthreads();
#pragma unroll
        for (int kt = 0; kt < 4; kt++) {
            uint32_t abase = (wo * 72 + kt * 16) * 2 + aoff2;
            uint32_t gh[4], gl[4];
            ldmx4(gh, smb + SM_GH + abase);
            ldmx4(gl, smb + SM_GL + abase);
#pragma unroll
            for (int nt = 0; nt < 2; nt++) {
                uint32_t bbase = ((wk + nt * 8) * 72 + kt * 16) * 2 + boff2;
                uint32_t bh[2], bl[2];
                ldmx2(bh, smb + SM_BASH + bbase);
                ldmx2(bl, smb + SM_BASL + bbase);
                mma_bf16(facc[nt], gh, bh);
                mma_bf16(facc[nt], gl, bh);
                mma_bf16(facc[nt], gh, bl);
            }
        }
        __syncthreads();
    }
    float* fp = g_fpart + (size_t)(s * BB + b) * WW * 32;
#pragma unroll
    for (int nt = 0; nt < 2; nt++) {
        int k = wk + nt * 8 + cc;
        *(float2*)&fp[(wo + cr) * 32 + k]     = make_float2(facc[nt][0], facc[nt][1]);
        *(float2*)&fp[(wo + cr + 8) * 32 + k] = make_float2(facc[nt][2], facc[nt][3]);
    }
}

// ---- HMMA final projection: out = gelu(v @ pw1 + b1) @ pw2 + b2 ----
// A: [128 t][72] bf16 hi/lo (v transpose), B: [128 j][72] bf16 hi/lo (pw1 transpose)
#define KP2     72
#define SM2_AH  0
#define SM2_AL  18432
#define SM2_BH  36864
#define SM2_BL  55296
#define SM2_PART 73728
#define SMEM_PJ  (73728 + 1024)
__global__ void __launch_bounds__(256, 2) k_proj(const float* __restrict__ pb1,
                                                 const float* __restrict__ pw2,
                                                 const float* __restrict__ pb2,
                                                 float* __restrict__ out) {
    extern __shared__ __align__(16) char sm[];
    uint32_t smb = smem_u32(sm);
    float* part = (float*)(sm + SM2_PART);   // [2][128]
    int b = blockIdx.x;
    int t0 = blockIdx.y * 128;
    int tid = threadIdx.x, wid = tid >> 5, lane = tid & 31;

    // A: v transpose fill (128 t x 64 i)
#pragma unroll
    for (int r = 0; r < 4; r++) {
        int idx = tid + 256 * r;
        int ip = idx >> 5, tq = idx & 31, i = ip * 2;
        float4 fa = *(const float4*)&g_v1[(size_t)(b * WW + i) * NTP + t0 + tq * 4];
        float4 fb = *(const float4*)&g_v1[(size_t)(b * WW + i + 1) * NTP + t0 + tq * 4];
        float va[4] = {fa.x, fa.y, fa.z, fa.w};
        float vb[4] = {fb.x, fb.y, fb.z, fb.w};
#pragma unroll
        for (int q = 0; q < 4; q++) {
            int t = tq * 4 + q;
            uint32_t lo;
            uint32_t hi = pack_hl(va[q], vb[q], lo);
            *(uint32_t*)(sm + SM2_AH + (t * KP2 + i) * 2) = hi;
            *(uint32_t*)(sm + SM2_AL + (t * KP2 + i) * 2) = lo;
        }
    }
    // B: precomputed pw1 transpose (128 j x 32 pairs)
#pragma unroll
    for (int r = 0; r < 16; r++) {
        int idx = tid + 256 * r;
        int j = idx >> 5, ip = idx & 31;
        *(uint32_t*)(sm + SM2_BH + (j * KP2 + 2 * ip) * 2) = g_pw1h2[idx];
        *(uint32_t*)(sm + SM2_BL + (j * KP2 + 2 * ip) * 2) = g_pw1l2[idx];
    }
    __syncthreads();

    int wT = (wid >> 1) * 32;
    int jG = (wid & 1) * 64;
    float acc[2][8][4];
#pragma unroll
    for (int mt = 0; mt < 2; mt++)
#pragma unroll
        for (int nt = 0; nt < 8; nt++)
#pragma unroll
            for (int c = 0; c < 4; c++) acc[mt][nt][c] = 0.f;

    uint32_t aoff = ((lane & 15) * KP2 + (lane >> 4) * 8) * 2;
    uint32_t boff = ((lane & 7) * KP2 + ((lane >> 3) & 1) * 8) * 2;
#pragma unroll
    for (int kt = 0; kt < 4; kt++) {
        int k0 = kt * 16;
        uint32_t ah[2][4], al[2][4];
#pragma unroll
        for (int mt = 0; mt < 2; mt++) {
            uint32_t base = ((wT + mt * 16) * KP2 + k0) * 2 + aoff;
            ldmx4(ah[mt], smb + SM2_AH + base);
            ldmx4(al[mt], smb + SM2_AL + base);
        }
#pragma unroll
        for (int nt = 0; nt < 8; nt++) {
            uint32_t bb = ((jG + nt * 8) * KP2 + k0) * 2 + boff;
            uint32_t bh[2], bl[2];
            ldmx2(bh, smb + SM2_BH + bb);
            ldmx2(bl, smb + SM2_BL + bb);
#pragma unroll
            for (int mt = 0; mt < 2; mt++) {
                mma_bf16(acc[mt][nt], ah[mt], bh);
                mma_bf16(acc[mt][nt], al[mt], bh);
                mma_bf16(acc[mt][nt], ah[mt], bl);
            }
        }
    }

    int cr = lane >> 2, cc = (lane & 3) * 2;
    float s[4] = {};   // [mt*2 + rowhalf]
#pragma unroll
    for (int nt = 0; nt < 8; nt++) {
        int j = jG + nt * 8 + cc;
        float b1a = __ldg(&pb1[j]),  b1b = __ldg(&pb1[j + 1]);
        float w2a = __ldg(&pw2[j]),  w2b = __ldg(&pw2[j + 1]);
#pragma unroll
        for (int mt = 0; mt < 2; mt++) {
            s[mt * 2 + 0] = fmaf(gelu_f(acc[mt][nt][0] + b1a), w2a,
                            fmaf(gelu_f(acc[mt][nt][1] + b1b), w2b, s[mt * 2 + 0]));
            s[mt * 2 + 1] = fmaf(gelu_f(acc[mt][nt][2] + b1a), w2a,
                            fmaf(gelu_f(acc[mt][nt][3] + b1b), w2b, s[mt * 2 + 1]));
        }
    }
#pragma unroll
    for (int m = 1; m <= 2; m <<= 1)
#pragma unroll
        for (int a = 0; a < 4; a++)
            s[a] += __shfl_xor_sync(0xffffffffu, s[a], m);
    if ((lane & 3) == 0) {
        int jh = wid & 1;
        part[jh * 128 + wT + cr]      = s[0];
        part[jh * 128 + wT + cr + 8]  = s[1];
        part[jh * 128 + wT + 16 + cr] = s[2];
        part[jh * 128 + wT + 24 + cr] = s[3];
    }
    __syncthreads();
    if (tid < 128) {
        float b2 = __ldg(&pb2[0]);
        out[b * FNSEQ + t0 + tid] = part[tid] + part[128 + tid] + b2;
    }
}

extern "C" void kernel_launch(void* const* d_in, const int* in_sizes, int n_in,
                              void* d_out, int out_size) {
    const float* x   = (const float*)d_in[0];
    const float* lw  = (const float*)d_in[1];
    const float* lb  = (const float*)d_in[2];
    const float* kr  = (const float*)d_in[3];
    const float* ki  = (const float*)d_in[4];
    const float* cw  = (const float*)d_in[5];
    const float* cb  = (const float*)d_in[6];
    const float* pw1 = (const float*)d_in[7];
    const float* pb1 = (const float*)d_in[8];
    const float* pw2 = (const float*)d_in[9];
    const float* pb2 = (const float*)d_in[10];
    float* out = (float*)d_out;

    static int attr_done = 0;
    if (!attr_done) {
        cudaFuncSetAttribute(k_pt, cudaFuncAttributeMaxDynamicSharedMemorySize, SMEM_PT);
        cudaFuncSetAttribute(k_proj, cudaFuncAttributeMaxDynamicSharedMemorySize, SMEM_PJ);
        attr_done = 1;
    }

    k_basis<<<(NTP + 127) / 128, 128>>>();
    k_prep<<<(5 * 64 * 32 + 127) / 128, 128>>>(cw);
    k_prep2<<<(128 * 32 + 127) / 128, 128>>>(pw1);
    k_lift<<<dim3(BB, (NTP + 127) / 128), 128>>>(x, lw, lb);
    k_fwd<<<dim3(BB, NSPL), 128>>>();
    for (int l = 0; l < 5; l++) {
        int src = l & 1;
        k_mix<<<BB, 1024>>>(kr + l * WW * WW * NMD, ki + l * WW * WW * NMD);
        k_pt<<<dim3(BB, NTP / 128), 256, SMEM_PT>>>(src, l, (l < 4) ? 1 : 0,
                                                    cb + l * WW);
    }
    k_proj<<<dim3(BB, FNSEQ / 128), 256, SMEM_PJ>>>(pb1, pw2, pb2, out);
}

// round 16
// speedup vs baseline: 2.6570x; 1.2623x over previous
#include <cuda_runtime.h>
#include <cuda_bf16.h>
#include <cstdint>

#define BB    64
#define WW    64
#define FNSEQ 8192
#define NTR   8201
#define NTP   8320
#define NMD   16
#define NSPL  65

// bf16 hi/lo pair images: [buf][b][s][t(128)][ip(32)] — pairs along channel i
__device__ uint32_t g_imh[2][BB][NSPL][128][32];
__device__ uint32_t g_iml[2][BB][NSPL][128][32];
__device__ uint32_t g_bh2[NTP * 16];           // bf16-pair basis hi [t][kp] (A layout)
__device__ uint32_t g_bl2[NTP * 16];           // lo
__device__ __nv_bfloat16 g_bthT[32 * NTP];     // bf16 basis hi [k][t] (B layout)
__device__ __nv_bfloat16 g_btlT[32 * NTP];     // lo
__device__ uint32_t g_cwh2[5 * 2048];          // bf16-pair conv w hi [l][o][ip]
__device__ uint32_t g_cwl2[5 * 2048];          // lo
__device__ uint32_t g_pw1h2[128 * 32];         // bf16-pair proj_w1 hi [j][ip]
__device__ uint32_t g_pw1l2[128 * 32];         // lo
__device__ __nv_bfloat16 g_abh[BB * WW * 32];  // [b][o][kk] hi
__device__ __nv_bfloat16 g_abl[BB * WW * 32];  // lo
__device__ float g_fpart[NSPL * BB * WW * 32];

__device__ __forceinline__ float gelu_f(float x) {
    return 0.5f * x * (1.0f + erff(x * 0.70710678118654752f));
}
__device__ __forceinline__ uint32_t smem_u32(const void* p) {
    uint32_t a;
    asm("{ .reg .u64 t; cvta.to.shared.u64 t, %1; cvt.u32.u64 %0, t; }" : "=r"(a) : "l"(p));
    return a;
}
__device__ __forceinline__ uint32_t pack_bf(__nv_bfloat16 a, __nv_bfloat16 b) {
    return (uint32_t)__bfloat16_as_ushort(a) | ((uint32_t)__bfloat16_as_ushort(b) << 16);
}
__device__ __forceinline__ uint32_t pack_hl(float v0, float v1, uint32_t& lo) {
    __nv_bfloat16 h0 = __float2bfloat16(v0), h1 = __float2bfloat16(v1);
    lo = pack_bf(__float2bfloat16(v0 - __bfloat162float(h0)),
                 __float2bfloat16(v1 - __bfloat162float(h1)));
    return pack_bf(h0, h1);
}
__device__ __forceinline__ void ldmx4(uint32_t* d, uint32_t addr) {
    asm volatile("ldmatrix.sync.aligned.m8n8.x4.shared.b16 {%0,%1,%2,%3}, [%4];"
                 : "=r"(d[0]), "=r"(d[1]), "=r"(d[2]), "=r"(d[3]) : "r"(addr));
}
__device__ __forceinline__ void ldmx2(uint32_t* d, uint32_t addr) {
    asm volatile("ldmatrix.sync.aligned.m8n8.x2.shared.b16 {%0,%1}, [%2];"
                 : "=r"(d[0]), "=r"(d[1]) : "r"(addr));
}
__device__ __forceinline__ void mma_bf16(float* c, const uint32_t* a, const uint32_t* b) {
    asm volatile(
        "mma.sync.aligned.m16n8k16.row.col.f32.bf16.bf16.f32 "
        "{%0,%1,%2,%3}, {%4,%5,%6,%7}, {%8,%9}, {%0,%1,%2,%3};"
        : "+f"(c[0]), "+f"(c[1]), "+f"(c[2]), "+f"(c[3])
        : "r"(a[0]), "r"(a[1]), "r"(a[2]), "r"(a[3]), "r"(b[0]), "r"(b[1]));
}

__global__ void k_basis() {
    int t = blockIdx.x * 128 + threadIdx.x;
    if (t >= NTP) return;
    float vals[32];
#pragma unroll
    for (int k = 0; k < NMD; k++) {
        int r = (k * t) % NTR;
        float ang = (float)((double)r * (6.283185307179586 / (double)NTR));
        float s, c;
        sincosf(ang, &s, &c);
        vals[k] = c;
        vals[NMD + k] = s;
    }
#pragma unroll
    for (int kp = 0; kp < 16; kp++) {
        uint32_t lo;
        g_bh2[t * 16 + kp] = pack_hl(vals[2 * kp], vals[2 * kp + 1], lo);
        g_bl2[t * 16 + kp] = lo;
    }
#pragma unroll
    for (int k = 0; k < 32; k++) {
        float v = vals[k];
        __nv_bfloat16 h = __float2bfloat16(v);
        g_bthT[k * NTP + t] = h;
        g_btlT[k * NTP + t] = __float2bfloat16(v - __bfloat162float(h));
    }
}

__global__ void k_prep(const float* __restrict__ cw) {
    int idx = blockIdx.x * 128 + threadIdx.x;   // 5*64*32
    if (idx >= 5 * 64 * 32) return;
    int l = idx >> 11, rem = idx & 2047;
    int o = rem >> 5, ip = rem & 31, i = ip * 2;
    uint32_t lo;
    uint32_t hi = pack_hl(cw[(l * WW + o) * WW + i], cw[(l * WW + o) * WW + i + 1], lo);
    g_cwh2[idx] = hi;
    g_cwl2[idx] = lo;
}

__global__ void k_prep2(const float* __restrict__ pw1) {
    int idx = blockIdx.x * 128 + threadIdx.x;   // 128*32
    if (idx >= 128 * 32) return;
    int j = idx >> 5, ip = idx & 31, i = ip * 2;
    uint32_t lo;
    uint32_t hi = pack_hl(pw1[i * 128 + j], pw1[(i + 1) * 128 + j], lo);
    g_pw1h2[idx] = hi;
    g_pw1l2[idx] = lo;
}

// shared-memory layout constants (k_pt and k_lift share the epilogue regions)
#define CST     133
#define KP      104
#define SM_CB   0
#define SM_AH   256
#define SM_AL   26880
#define SM_BH   53504
#define SM_BL   66816
#define SM_GH   53504
#define SM_GL   62720
#define SM_BASH 71936
#define SM_BASL 76544
#define SMEM_PT 81152

// fused forward-DFT partial: F_part[o,k] = sum_t Csm[o][t] * basis[k][t0+t]
__device__ __forceinline__ void dft_store(char* sm, uint32_t smb,
                                          const float* __restrict__ Csm,
                                          int b, int s, int t0,
                                          int tid, int wid, int lane) {
    int wo = (wid >> 1) * 16;
    int wk = (wid & 1) * 16;
    int cr = lane >> 2, cc = (lane & 3) * 2;
    float facc[2][4] = {};
    uint32_t aoff2 = ((lane & 15) * 72 + (lane >> 4) * 8) * 2;
    uint32_t boff2 = ((lane & 7) * 72 + ((lane >> 3) & 1) * 8) * 2;
#pragma unroll
    for (int h = 0; h < 2; h++) {
        int th0 = h * 64;
#pragma unroll
        for (int r = 0; r < 8; r++) {
            int idx = tid + 256 * r;
            int o = idx >> 5, tp = idx & 31;
            int t = th0 + tp * 2;
            float g0 = Csm[o * CST + t];
            float g1 = Csm[o * CST + t + 1];
            if (t0 + t >= NTR) g0 = 0.f;
            if (t0 + t + 1 >= NTR) g1 = 0.f;
            uint32_t lo;
            uint32_t hi = pack_hl(g0, g1, lo);
            *(uint32_t*)(sm + SM_GH + (o * 72 + tp * 2) * 2) = hi;
            *(uint32_t*)(sm + SM_GL + (o * 72 + tp * 2) * 2) = lo;
        }
#pragma unroll
        for (int r = 0; r < 4; r++) {
            int idx = tid + 256 * r;
            int k = idx >> 5, tp = idx & 31;
            int tg = t0 + th0 + tp * 2;
            *(uint32_t*)(sm + SM_BASH + (k * 72 + tp * 2) * 2) =
                *(const uint32_t*)&g_bthT[k * NTP + tg];
            *(uint32_t*)(sm + SM_BASL + (k * 72 + tp * 2) * 2) =
                *(const uint32_t*)&g_btlT[k * NTP + tg];
        }
        __syncthreads();
#pragma unroll
        for (int kt = 0; kt < 4; kt++) {
            uint32_t abase = (wo * 72 + kt * 16) * 2 + aoff2;
            uint32_t gh[4], gl[4];
            ldmx4(gh, smb + SM_GH + abase);
            ldmx4(gl, smb + SM_GL + abase);
#pragma unroll
            for (int nt = 0; nt < 2; nt++) {
                uint32_t bbase = ((wk + nt * 8) * 72 + kt * 16) * 2 + boff2;
                uint32_t bh[2], bl[2];
                ldmx2(bh, smb + SM_BASH + bbase);
                ldmx2(bl, smb + SM_BASL + bbase);
                mma_bf16(facc[nt], gh, bh);
                mma_bf16(facc[nt], gl, bh);
                mma_bf16(facc[nt], gh, bl);
            }
        }
        __syncthreads();
    }
    float* fp = g_fpart + (size_t)(s * BB + b) * WW * 32;
#pragma unroll
    for (int nt = 0; nt < 2; nt++) {
        int k = wk + nt * 8 + cc;
        *(float2*)&fp[(wo + cr) * 32 + k]     = make_float2(facc[nt][0], facc[nt][1]);
        *(float2*)&fp[(wo + cr + 8) * 32 + k] = make_float2(facc[nt][2], facc[nt][3]);
    }
}

// lift + layer-0 image write + layer-0 forward-DFT partials
__global__ void __launch_bounds__(256, 2) k_lift(const float* __restrict__ x,
                                                 const float* __restrict__ lw,
                                                 const float* __restrict__ lb) {
    extern __shared__ char sm[];
    uint32_t smb = smem_u32(sm);
    float* vs = (float*)(sm + SM_AH);     // [64 i][CST]
    int b = blockIdx.x, s = blockIdx.y;
    int t0 = s * 128;
    int tid = threadIdx.x, wid = tid >> 5, lane = tid & 31;
    int tl = tid & 127, ih = (tid >> 7) * 32;
    int tg = t0 + tl;
    float x0 = 0.f, x1 = 0.f;
    bool live = (tg < FNSEQ);
    if (live) {
        x0 = x[(b * FNSEQ + tg) * 2 + 0];
        x1 = x[(b * FNSEQ + tg) * 2 + 1];
    }
#pragma unroll
    for (int i = 0; i < 32; i++) {
        int ii = ih + i;
        float v = 0.f;
        if (live)
            v = fmaf(x0, __ldg(&lw[ii]), fmaf(x1, __ldg(&lw[WW + ii]), __ldg(&lb[ii])));
        vs[ii * CST + tl] = v;
    }
    __syncthreads();
#pragma unroll
    for (int r = 0; r < 16; r++) {
        int idx = tid + 256 * r;
        int t = idx >> 5, ip = idx & 31;
        float g0 = vs[(2 * ip) * CST + t];
        float g1 = vs[(2 * ip + 1) * CST + t];
        uint32_t lo;
        uint32_t hi = pack_hl(g0, g1, lo);
        g_imh[0][b][s][t][ip] = hi;
        g_iml[0][b][s][t][ip] = lo;
    }
    dft_store(sm, smb, vs, b, s, t0, tid, wid, lane);
}

// mode mixing + irfft fold -> bf16 hi/lo coefficient tables (sums 65 partials)
__global__ void __launch_bounds__(1024) k_mix(const float* __restrict__ kr,
                                              const float* __restrict__ ki) {
    __shared__ float Fs[WW][32];
    int b = blockIdx.x, tid = threadIdx.x;
#pragma unroll
    for (int r = 0; r < 2; r++) {
        int idx = tid + 1024 * r;
        float sum = 0.f;
        for (int s = 0; s < NSPL; s++)
            sum += g_fpart[(size_t)(s * BB + b) * WW * 32 + idx];
        ((float*)Fs)[idx] = sum;
    }
    __syncthreads();
    int k = tid & 15, o = tid >> 4;
    float ck = (k == 0) ? (1.0f / (float)NTR) : (2.0f / (float)NTR);
    float pr = 0.f, pi = 0.f;
#pragma unroll 4
    for (int i = 0; i < WW; i++) {
        float fr = Fs[i][k];
        float fs = Fs[i][NMD + k];
        float krv = __ldg(&kr[(i * WW + o) * NMD + k]);
        float kiv = __ldg(&ki[(i * WW + o) * NMD + k]);
        pr = fmaf(fr, krv, fmaf(fs, kiv, pr));
        pi = fmaf(fr, kiv, fmaf(-fs, krv, pi));
    }
    float a_cos = ck * pr, a_sin = -ck * pi;
    int base = ((b << 6) + o) * 32;
    __nv_bfloat16 hc = __float2bfloat16(a_cos);
    __nv_bfloat16 hs = __float2bfloat16(a_sin);
    g_abh[base + k] = hc;
    g_abl[base + k] = __float2bfloat16(a_cos - __bfloat162float(hc));
    g_abh[base + NMD + k] = hs;
    g_abl[base + NMD + k] = __float2bfloat16(a_sin - __bfloat162float(hs));
}

// ---- mma.sync fused layer + image write + fused next-layer forward DFT ----
__global__ void __launch_bounds__(256, 2) k_pt(int src, int l, int do_dft,
                                               const float* __restrict__ cb) {
    extern __shared__ char sm[];
    uint32_t smb = smem_u32(sm);
    float* cbS = (float*)(sm + SM_CB);
    float* Csm = (float*)(sm + SM_AH);          // overlay, [64 o][CST]
    int b = blockIdx.x;
    int s = blockIdx.y;
    int t0 = s * 128;
    int tid = threadIdx.x, wid = tid >> 5, lane = tid & 31;
    int dst = src ^ 1;

    if (tid < 64) cbS[tid] = cb[tid];
    // A: v-channel image copy (cols 0..63) — pure float4 copies
#pragma unroll
    for (int r = 0; r < 4; r++) {
        int idx = tid + 256 * r;              // 1024 float4-units
        int t = idx >> 3, q = idx & 7;
        *(float4*)(sm + SM_AH + (t * KP + q * 8) * 2) =
            *(const float4*)&g_imh[src][b][s][t][q * 4];
        *(float4*)(sm + SM_AL + (t * KP + q * 8) * 2) =
            *(const float4*)&g_iml[src][b][s][t][q * 4];
    }
    // A: basis (cols 64..95)
#pragma unroll
    for (int r = 0; r < 8; r++) {
        int idx = tid + 256 * r;
        int t = idx >> 4, kp = idx & 15;
        *(uint32_t*)(sm + SM_AH + (t * KP + 64 + 2 * kp) * 2) = g_bh2[(t0 + t) * 16 + kp];
        *(uint32_t*)(sm + SM_AL + (t * KP + 64 + 2 * kp) * 2) = g_bl2[(t0 + t) * 16 + kp];
    }
    // B: conv weights (cols 0..63)
#pragma unroll
    for (int r = 0; r < 8; r++) {
        int idx = tid + 256 * r;
        int o = idx >> 5, ip = idx & 31;
        *(uint32_t*)(sm + SM_BH + (o * KP + 2 * ip) * 2) = g_cwh2[l * 2048 + idx];
        *(uint32_t*)(sm + SM_BL + (o * KP + 2 * ip) * 2) = g_cwl2[l * 2048 + idx];
    }
    // B: ab coefficients (cols 64..95)
#pragma unroll
    for (int r = 0; r < 4; r++) {
        int idx = tid + 256 * r;
        int o = idx >> 4, kp = idx & 15;
        int gi = ((b << 6) + o) * 32 + 2 * kp;
        *(uint32_t*)(sm + SM_BH + (o * KP + 64 + 2 * kp) * 2) =
            *(const uint32_t*)&g_abh[gi];
        *(uint32_t*)(sm + SM_BL + (o * KP + 64 + 2 * kp) * 2) =
            *(const uint32_t*)&g_abl[gi];
    }
    __syncthreads();

    int wT = (wid >> 1) * 32;
    int oG = (wid & 1) * 32;
    float acc[2][4][4];
#pragma unroll
    for (int mt = 0; mt < 2; mt++)
#pragma unroll
        for (int nt = 0; nt < 4; nt++)
#pragma unroll
            for (int c = 0; c < 4; c++) acc[mt][nt][c] = 0.f;

    uint32_t aoff = ((lane & 15) * KP + (lane >> 4) * 8) * 2;
    uint32_t boff = ((lane & 7) * KP + ((lane >> 3) & 1) * 8) * 2;
#pragma unroll
    for (int kt = 0; kt < 6; kt++) {
        int k0 = kt * 16;
        uint32_t ah[2][4], al[2][4];
#pragma unroll
        for (int mt = 0; mt < 2; mt++) {
            uint32_t base = ((wT + mt * 16) * KP + k0) * 2 + aoff;
            ldmx4(ah[mt], smb + SM_AH + base);
            ldmx4(al[mt], smb + SM_AL + base);
        }
#pragma unroll
        for (int nt = 0; nt < 4; nt++) {
            uint32_t bb = ((oG + nt * 8) * KP + k0) * 2 + boff;
            uint32_t bh[2], bl[2];
            ldmx2(bh, smb + SM_BH + bb);
            ldmx2(bl, smb + SM_BL + bb);
#pragma unroll
            for (int mt = 0; mt < 2; mt++) {
                mma_bf16(acc[mt][nt], ah[mt], bh);
                mma_bf16(acc[mt][nt], al[mt], bh);
                mma_bf16(acc[mt][nt], ah[mt], bl);
            }
        }
    }
    __syncthreads();

    // bias + GELU in fragments, write gelu'd values to Csm
    int cr = lane >> 2, cc = (lane & 3) * 2;
#pragma unroll
    for (int mt = 0; mt < 2; mt++)
#pragma unroll
        for (int nt = 0; nt < 4; nt++) {
            int t = wT + mt * 16 + cr;
            int o = oG + nt * 8 + cc;
            float b0 = cbS[o], b1v = cbS[o + 1];
            Csm[o * CST + t]           = gelu_f(acc[mt][nt][0] + b0);
            Csm[(o + 1) * CST + t]     = gelu_f(acc[mt][nt][1] + b1v);
            Csm[o * CST + t + 8]       = gelu_f(acc[mt][nt][2] + b0);
            Csm[(o + 1) * CST + t + 8] = gelu_f(acc[mt][nt][3] + b1v);
        }
    __syncthreads();

    // image store: bf16 hi/lo pairs along o (next layer's i)
#pragma unroll
    for (int r = 0; r < 16; r++) {
        int idx = tid + 256 * r;
        int t = idx >> 5, ip = idx & 31;
        float g0 = Csm[(2 * ip) * CST + t];
        float g1 = Csm[(2 * ip + 1) * CST + t];
        uint32_t lo;
        uint32_t hi = pack_hl(g0, g1, lo);
        g_imh[dst][b][s][t][ip] = hi;
        g_iml[dst][b][s][t][ip] = lo;
    }

    if (!do_dft) return;
    dft_store(sm, smb, Csm, b, s, t0, tid, wid, lane);
}

// ---- HMMA final projection: out = gelu(v @ pw1 + b1) @ pw2 + b2 ----
#define KP2      72
#define SM2_AH   0
#define SM2_AL   18432
#define SM2_BH   36864
#define SM2_BL   55296
#define SM2_PART 73728
#define SMEM_PJ  (73728 + 1024)
__global__ void __launch_bounds__(256, 2) k_proj(const float* __restrict__ pb1,
                                                 const float* __restrict__ pw2,
                                                 const float* __restrict__ pb2,
                                                 float* __restrict__ out) {
    extern __shared__ char sm[];
    uint32_t smb = smem_u32(sm);
    float* part = (float*)(sm + SM2_PART);   // [2][128]
    int b = blockIdx.x;
    int s = blockIdx.y;
    int t0 = s * 128;
    int tid = threadIdx.x, wid = tid >> 5, lane = tid & 31;

    // A: image copy (final layer output lives in buffer 1)
#pragma unroll
    for (int r = 0; r < 4; r++) {
        int idx = tid + 256 * r;
        int t = idx >> 3, q = idx & 7;
        *(float4*)(sm + SM2_AH + (t * KP2 + q * 8) * 2) =
            *(const float4*)&g_imh[1][b][s][t][q * 4];
        *(float4*)(sm + SM2_AL + (t * KP2 + q * 8) * 2) =
            *(const float4*)&g_iml[1][b][s][t][q * 4];
    }
    // B: precomputed pw1 transpose (128 j x 32 pairs)
#pragma unroll
    for (int r = 0; r < 16; r++) {
        int idx = tid + 256 * r;
        int j = idx >> 5, ip = idx & 31;
        *(uint32_t*)(sm + SM2_BH + (j * KP2 + 2 * ip) * 2) = g_pw1h2[idx];
        *(uint32_t*)(sm + SM2_BL + (j * KP2 + 2 * ip) * 2) = g_pw1l2[idx];
    }
    __syncthreads();

    int wT = (wid >> 1) * 32;
    int jG = (wid & 1) * 64;
    float acc[2][8][4];
#pragma unroll
    for (int mt = 0; mt < 2; mt++)
#pragma unroll
        for (int nt = 0; nt < 8; nt++)
#pragma unroll
            for (int c = 0; c < 4; c++) acc[mt][nt][c] = 0.f;

    uint32_t aoff = ((lane & 15) * KP2 + (lane >> 4) * 8) * 2;
    uint32_t boff = ((lane & 7) * KP2 + ((lane >> 3) & 1) * 8) * 2;
#pragma unroll
    for (int kt = 0; kt < 4; kt++) {
        int k0 = kt * 16;
        uint32_t ah[2][4], al[2][4];
#pragma unroll
        for (int mt = 0; mt < 2; mt++) {
            uint32_t base = ((wT + mt * 16) * KP2 + k0) * 2 + aoff;
            ldmx4(ah[mt], smb + SM2_AH + base);
            ldmx4(al[mt], smb + SM2_AL + base);
        }
#pragma unroll
        for (int nt = 0; nt < 8; nt++) {
            uint32_t bb = ((jG + nt * 8) * KP2 + k0) * 2 + boff;
            uint32_t bh[2], bl[2];
            ldmx2(bh, smb + SM2_BH + bb);
            ldmx2(bl, smb + SM2_BL + bb);
#pragma unroll
            for (int mt = 0; mt < 2; mt++) {
                mma_bf16(acc[mt][nt], ah[mt], bh);
                mma_bf16(acc[mt][nt], al[mt], bh);
                mma_bf16(acc[mt][nt], ah[mt], bl);
            }
        }
    }

    int cr = lane >> 2, cc = (lane & 3) * 2;
    float s4[4] = {};
#pragma unroll
    for (int nt = 0; nt < 8; nt++) {
        int j = jG + nt * 8 + cc;
        float b1a = __ldg(&pb1[j]),  b1b = __ldg(&pb1[j + 1]);
        float w2a = __ldg(&pw2[j]),  w2b = __ldg(&pw2[j + 1]);
#pragma unroll
        for (int mt = 0; mt < 2; mt++) {
            s4[mt * 2 + 0] = fmaf(gelu_f(acc[mt][nt][0] + b1a), w2a,
                             fmaf(gelu_f(acc[mt][nt][1] + b1b), w2b, s4[mt * 2 + 0]));
            s4[mt * 2 + 1] = fmaf(gelu_f(acc[mt][nt][2] + b1a), w2a,
                             fmaf(gelu_f(acc[mt][nt][3] + b1b), w2b, s4[mt * 2 + 1]));
        }
    }
#pragma unroll
    for (int m = 1; m <= 2; m <<= 1)
#pragma unroll
        for (int a = 0; a < 4; a++)
            s4[a] += __shfl_xor_sync(0xffffffffu, s4[a], m);
    if ((lane & 3) == 0) {
        int jh = wid & 1;
        part[jh * 128 + wT + cr]      = s4[0];
        part[jh * 128 + wT + cr + 8]  = s4[1];
        part[jh * 128 + wT + 16 + cr] = s4[2];
        part[jh * 128 + wT + 24 + cr] = s4[3];
    }
    __syncthreads();
    if (tid < 128) {
        float b2 = __ldg(&pb2[0]);
        out[b * FNSEQ + t0 + tid] = part[tid] + part[128 + tid] + b2;
    }
}

extern "C" void kernel_launch(void* const* d_in, const int* in_sizes, int n_in,
                              void* d_out, int out_size) {
    const float* x   = (const float*)d_in[0];
    const float* lw  = (const float*)d_in[1];
    const float* lb  = (const float*)d_in[2];
    const float* kr  = (const float*)d_in[3];
    const float* ki  = (const float*)d_in[4];
    const float* cw  = (const float*)d_in[5];
    const float* cb  = (const float*)d_in[6];
    const float* pw1 = (const float*)d_in[7];
    const float* pb1 = (const float*)d_in[8];
    const float* pw2 = (const float*)d_in[9];
    const float* pb2 = (const float*)d_in[10];
    float* out = (float*)d_out;

    static int attr_done = 0;
    if (!attr_done) {
        cudaFuncSetAttribute(k_pt, cudaFuncAttributeMaxDynamicSharedMemorySize, SMEM_PT);
        cudaFuncSetAttribute(k_lift, cudaFuncAttributeMaxDynamicSharedMemorySize, SMEM_PT);
        cudaFuncSetAttribute(k_proj, cudaFuncAttributeMaxDynamicSharedMemorySize, SMEM_PJ);
        attr_done = 1;
    }

    k_basis<<<(NTP + 127) / 128, 128>>>();
    k_prep<<<(5 * 64 * 32 + 127) / 128, 128>>>(cw);
    k_prep2<<<(128 * 32 + 127) / 128, 128>>>(pw1);
    k_lift<<<dim3(BB, NSPL), 256, SMEM_PT>>>(x, lw, lb);
    for (int l = 0; l < 5; l++) {
        int src = l & 1;
        k_mix<<<BB, 1024>>>(kr + l * WW * WW * NMD, ki + l * WW * WW * NMD);
        k_pt<<<dim3(BB, NSPL), 256, SMEM_PT>>>(src, l, (l < 4) ? 1 : 0,
                                               cb + l * WW);
    }
    k_proj<<<dim3(BB, FNSEQ / 128), 256, SMEM_PJ>>>(pb1, pw2, pb2, out);
}